// round 2
// baseline (speedup 1.0000x reference)
#include <cuda_runtime.h>

#define HH 96
#define WW 96
#define HWN 9216
#define CN 256
#define BB 2
#define NOUT 648
#define NPAD 704
#define KBIG 2304

// ---------------- scratch (device globals; no allocation) ----------------
__device__ float g_qpre[BB * CN * HWN];      // pre-LN projected query
__device__ float g_qchw[BB * CN * HWN];      // LN'd query, CHW
__device__ float g_qhwc[BB * HWN * CN];      // LN'd query, HWC (for gathers)
__device__ float g_conv[BB * NOUT * HWN];    // offsets+masks conv output
__device__ float g_Wpack[KBIG * NPAD];       // packed conv weights [k][n]
__device__ float g_bpack[NPAD];
__device__ float g_WA[CN * CN];              // in_w transposed [k][n]
__device__ float g_sW[BB * 3 * CN * 9];      // LN'd support (deform weights)
__device__ float g_pool[BB * 6 * 128];       // max-pooled support
__device__ float g_sim[BB * 24 * HWN];       // similarity maps

// ---------------- packing ----------------
__global__ void pack_wa(const float* __restrict__ inw) {
    int idx = blockIdx.x * 256 + threadIdx.x;   // 65536
    int k = idx >> 8, n = idx & 255;
    g_WA[k * CN + n] = inw[n * CN + k];
}

__global__ void pack_big(const float* __restrict__ ow1, const float* __restrict__ mw1,
                         const float* __restrict__ ow2, const float* __restrict__ mw2,
                         const float* __restrict__ ow4, const float* __restrict__ mw4,
                         const float* __restrict__ ob1, const float* __restrict__ mb1,
                         const float* __restrict__ ob2, const float* __restrict__ mb2,
                         const float* __restrict__ ob4, const float* __restrict__ mb4) {
    int idx = blockIdx.x * 256 + threadIdx.x;
    if (idx < KBIG * NPAD) {
        int k = idx / NPAD, n = idx - (idx / NPAD) * NPAD;
        float v = 0.f;
        if (n < NOUT) {
            int d = n / 216, r = n - d * 216;
            const float* w = (r < 144) ? (d == 0 ? ow1 : d == 1 ? ow2 : ow4)
                                       : (d == 0 ? mw1 : d == 1 ? mw2 : mw4);
            int oc = (r < 144) ? r : r - 144;
            v = w[oc * KBIG + k];
        }
        g_Wpack[k * NPAD + n] = v;
    }
    if (idx < NPAD) {
        float v = 0.f;
        if (idx < NOUT) {
            int d = idx / 216, r = idx - d * 216;
            const float* bb = (r < 144) ? (d == 0 ? ob1 : d == 1 ? ob2 : ob4)
                                        : (d == 0 ? mb1 : d == 1 ? mb2 : mb4);
            v = bb[(r < 144) ? r : r - 144];
        }
        g_bpack[idx] = v;
    }
}

// ---------------- 1x1 in-projection GEMM (q) ----------------
// M=9216/batch (BM=128), N=256 (BN=64), K=256 (BK=16), 256 threads, 8x4 micro
__global__ void gemm_in(const float* __restrict__ x, const float* __restrict__ bias) {
    __shared__ __align__(16) float As[16 * 64];
    __shared__ __align__(16) float Bs[16 * 128];
    int b = blockIdx.z;
    int m0 = blockIdx.x * 128, n0 = blockIdx.y * 64;
    int tid = threadIdx.x;
    int tn = tid & 15, tm = tid >> 4;
    int kk_ld = tid >> 4, q = tid & 15;
    float acc[8][4];
#pragma unroll
    for (int j = 0; j < 8; j++)
#pragma unroll
        for (int i = 0; i < 4; i++) acc[j][i] = 0.f;
    const float* xb = x + (size_t)b * CN * HWN;
    for (int k0 = 0; k0 < 256; k0 += 16) {
        *(float4*)&As[kk_ld * 64 + q * 4] =
            *(const float4*)&g_WA[(k0 + kk_ld) * CN + n0 + q * 4];
        const float* src = &xb[(k0 + kk_ld) * HWN + m0 + q * 8];
        *(float4*)&Bs[kk_ld * 128 + q * 8]     = *(const float4*)&src[0];
        *(float4*)&Bs[kk_ld * 128 + q * 8 + 4] = *(const float4*)&src[4];
        __syncthreads();
#pragma unroll
        for (int kk = 0; kk < 16; kk++) {
            float4 a  = *(const float4*)&As[kk * 64 + tn * 4];
            float4 b0 = *(const float4*)&Bs[kk * 128 + tm * 8];
            float4 b1 = *(const float4*)&Bs[kk * 128 + tm * 8 + 4];
            float av[4] = {a.x, a.y, a.z, a.w};
            float bv[8] = {b0.x, b0.y, b0.z, b0.w, b1.x, b1.y, b1.z, b1.w};
#pragma unroll
            for (int j = 0; j < 8; j++)
#pragma unroll
                for (int i = 0; i < 4; i++) acc[j][i] += bv[j] * av[i];
        }
        __syncthreads();
    }
#pragma unroll
    for (int i = 0; i < 4; i++) {
        int n = n0 + tn * 4 + i;
        float bi = bias[n];
        float* dst = &g_qpre[((size_t)b * CN + n) * HWN + m0 + tm * 8];
#pragma unroll
        for (int j = 0; j < 8; j++) dst[j] = acc[j][i] + bi;
    }
}

// ---------------- fused 3x3 conv GEMM (offsets + masks, all 3 dilations) ----------------
__global__ void gemm_big() {
    __shared__ __align__(16) float As[16 * 64];
    __shared__ __align__(16) float Bs[16 * 128];
    int b = blockIdx.z;
    int m0 = blockIdx.x * 128, n0 = blockIdx.y * 64;
    int tid = threadIdx.x;
    int tn = tid & 15, tm = tid >> 4;
    int kk_ld = tid >> 4, q = tid & 15;
    int ybuf[8], xbuf[8];
#pragma unroll
    for (int j = 0; j < 8; j++) {
        int pm = m0 + q * 8 + j;
        ybuf[j] = pm / 96;
        xbuf[j] = pm - ybuf[j] * 96;
    }
    float acc[8][4];
#pragma unroll
    for (int j = 0; j < 8; j++)
#pragma unroll
        for (int i = 0; i < 4; i++) acc[j][i] = 0.f;
    const float* qb = g_qchw + (size_t)b * CN * HWN;
    for (int k0 = 0; k0 < KBIG; k0 += 16) {
        *(float4*)&As[kk_ld * 64 + q * 4] =
            *(const float4*)&g_Wpack[(size_t)(k0 + kk_ld) * NPAD + n0 + q * 4];
        int k = k0 + kk_ld;
        int c = k / 9;
        int tap = k - c * 9;
        int t3 = tap / 3;
        int dty = t3 - 1, dtx = (tap - t3 * 3) - 1;
        const float* src = qb + c * HWN;
#pragma unroll
        for (int j = 0; j < 8; j++) {
            int yy = ybuf[j] + dty, xx = xbuf[j] + dtx;
            float v = 0.f;
            if ((unsigned)yy < 96u && (unsigned)xx < 96u) v = __ldg(&src[yy * 96 + xx]);
            Bs[kk_ld * 128 + q * 8 + j] = v;
        }
        __syncthreads();
#pragma unroll
        for (int kk = 0; kk < 16; kk++) {
            float4 a  = *(const float4*)&As[kk * 64 + tn * 4];
            float4 b0 = *(const float4*)&Bs[kk * 128 + tm * 8];
            float4 b1 = *(const float4*)&Bs[kk * 128 + tm * 8 + 4];
            float av[4] = {a.x, a.y, a.z, a.w};
            float bv[8] = {b0.x, b0.y, b0.z, b0.w, b1.x, b1.y, b1.z, b1.w};
#pragma unroll
            for (int j = 0; j < 8; j++)
#pragma unroll
                for (int i = 0; i < 4; i++) acc[j][i] += bv[j] * av[i];
        }
        __syncthreads();
    }
#pragma unroll
    for (int i = 0; i < 4; i++) {
        int n = n0 + tn * 4 + i;
        if (n >= NOUT) continue;
        float bi = g_bpack[n];
        float* dst = &g_conv[((size_t)b * NOUT + n) * HWN + m0 + tm * 8];
#pragma unroll
        for (int j = 0; j < 8; j++) dst[j] = acc[j][i] + bi;
    }
}

// ---------------- channel LayerNorm (q) + CHW/HWC dual write ----------------
__global__ void ln_kernel(const float* __restrict__ gam, const float* __restrict__ bet) {
    __shared__ float tile[32 * 257];
    __shared__ float red1[8][32], red2[8][32];
    __shared__ float mus[32], rvs[32];
    int tid = threadIdx.x;
    int pl = tid & 31, cg = tid >> 5;
    int pg0 = blockIdx.x * 32;
    int pg = pg0 + pl;
    int b = pg / HWN;
    int p = pg - b * HWN;
    float s1 = 0.f, s2 = 0.f;
#pragma unroll
    for (int i = 0; i < 32; i++) {
        int c = cg * 32 + i;
        float v = g_qpre[((size_t)b * CN + c) * HWN + p];
        tile[pl * 257 + c] = v;
        s1 += v; s2 += v * v;
    }
    red1[cg][pl] = s1; red2[cg][pl] = s2;
    __syncthreads();
    if (tid < 32) {
        float a = 0.f, bb = 0.f;
#pragma unroll
        for (int j = 0; j < 8; j++) { a += red1[j][tid]; bb += red2[j][tid]; }
        float mu = a * (1.f / 256.f);
        float var = bb * (1.f / 256.f) - mu * mu;
        mus[tid] = mu;
        rvs[tid] = rsqrtf(var + 1e-5f);
    }
    __syncthreads();
    float mu = mus[pl], rv = rvs[pl];
#pragma unroll
    for (int i = 0; i < 32; i++) {
        int c = cg * 32 + i;
        float val = (tile[pl * 257 + c] - mu) * rv * gam[c] + bet[c];
        g_qchw[((size_t)b * CN + c) * HWN + p] = val;
        tile[pl * 257 + c] = val;
    }
    __syncthreads();
#pragma unroll
    for (int i = 0; i < 32; i++) {
        int idx = tid + i * 256;
        int pp = idx >> 8, c = idx & 255;
        g_qhwc[(size_t)(pg0 + pp) * 256 + c] = tile[pp * 257 + c];
    }
}

// ---------------- support path: 1x1 proj + LN + maxpool ----------------
__global__ void support_kernel(const float* __restrict__ sup, const float* __restrict__ inb,
                               const float* __restrict__ gam, const float* __restrict__ bet) {
    __shared__ float xs[2304];
    __shared__ float ys[2304];
    __shared__ float stats[18];
    int bid = blockIdx.x;
    int b = bid / 3, ex = bid - b * 3;
    int tid = threadIdx.x;
    const float* sp = sup + (size_t)(b * 3 + ex) * 2304;
    for (int i = tid; i < 2304; i += 256) xs[i] = sp[i];
    __syncthreads();
    float acc[9];
#pragma unroll
    for (int pos = 0; pos < 9; pos++) acc[pos] = inb[tid];
    for (int k = 0; k < 256; k++) {
        float w = g_WA[k * 256 + tid];
#pragma unroll
        for (int pos = 0; pos < 9; pos++) acc[pos] += w * xs[k * 9 + pos];
    }
#pragma unroll
    for (int pos = 0; pos < 9; pos++) ys[tid * 9 + pos] = acc[pos];
    __syncthreads();
    if (tid < 9) {
        float s1 = 0.f, s2 = 0.f;
        for (int c = 0; c < 256; c++) { float v = ys[c * 9 + tid]; s1 += v; s2 += v * v; }
        float mu = s1 * (1.f / 256.f);
        float var = s2 * (1.f / 256.f) - mu * mu;
        stats[tid] = mu;
        stats[9 + tid] = rsqrtf(var + 1e-5f);
    }
    __syncthreads();
    float mx = -1e30f;
    float g = gam[tid], be = bet[tid];
#pragma unroll
    for (int pos = 0; pos < 9; pos++) {
        float v = (acc[pos] - stats[pos]) * stats[9 + pos] * g + be;
        g_sW[((size_t)(b * 3 + ex) * 256 + tid) * 9 + pos] = v;
        mx = fmaxf(mx, v);
    }
    int r = ex * 2 + (tid >> 7);
    g_pool[(b * 6 + r) * 128 + (tid & 127)] = mx;
}

// ---------------- mask softmax over 72 channels per pixel (in-place) ----------------
__global__ void softmax_kernel() {
    int p = blockIdx.x * 256 + threadIdx.x;
    int dz = blockIdx.y, b = blockIdx.z;
    float* base = g_conv + ((size_t)(b * NOUT) + dz * 216 + 144) * HWN + p;
    float mx = -1e30f;
    for (int i = 0; i < 72; i++) mx = fmaxf(mx, base[(size_t)i * HWN]);
    float s = 0.f;
    for (int i = 0; i < 72; i++) {
        float e = expf(base[(size_t)i * HWN] - mx);
        base[(size_t)i * HWN] = e;
        s += e;
    }
    float inv = 1.f / s;
    for (int i = 0; i < 72; i++) base[(size_t)i * HWN] *= inv;
}

// ---------------- sim0 (pooled 1x1 grouped branch) ----------------
__global__ void sim0_kernel() {
    __shared__ __align__(16) float psh[6 * 128];
    int b = blockIdx.y;
    int tid = threadIdx.x;
    int lane8 = tid & 7, pl = tid >> 3;
    int pg = blockIdx.x * 32 + pl;
    for (int i = tid; i < 768; i += 256) psh[i] = g_pool[b * 768 + i];
    __syncthreads();
    const float* qrow = g_qhwc + ((size_t)b * HWN + pg) * CN;
    float acc[6];
#pragma unroll
    for (int r = 0; r < 6; r++) acc[r] = 0.f;
#pragma unroll
    for (int r = 0; r < 6; r++) {
        int g = (r >= 3) ? 1 : 0;
#pragma unroll
        for (int qq = 0; qq < 4; qq++) {
            int f = lane8 + qq * 8;
            float4 qv = *(const float4*)&qrow[g * 128 + f * 4];
            float4 pv = *(const float4*)&psh[r * 128 + f * 4];
            acc[r] += qv.x * pv.x + qv.y * pv.y + qv.z * pv.z + qv.w * pv.w;
        }
    }
#pragma unroll
    for (int r = 0; r < 6; r++) {
        acc[r] += __shfl_xor_sync(0xffffffffu, acc[r], 1);
        acc[r] += __shfl_xor_sync(0xffffffffu, acc[r], 2);
        acc[r] += __shfl_xor_sync(0xffffffffu, acc[r], 4);
    }
    if (lane8 == 0) {
#pragma unroll
        for (int r = 0; r < 6; r++)
            g_sim[((size_t)b * 24 + r) * HWN + pg] = acc[r];
    }
}

// ---------------- deformable conv (one dilation per grid.z) ----------------
__device__ __forceinline__ void deform_og(
    int og, int py, int px, int p, int dil, int lane8,
    const float* __restrict__ offp, const float* __restrict__ mskp,
    const float* __restrict__ qb, const float* wsh,
    float& a0, float& a1, float& a2, int rbase) {
    int cb = og * 32 + lane8 * 4;
    int cgrp = (og & 3) * 32 + lane8 * 4;
#pragma unroll
    for (int tap = 0; tap < 9; tap++) {
        float dy = __ldg(&offp[(size_t)(og * 18 + tap * 2) * HWN + p]);
        float dx = __ldg(&offp[(size_t)(og * 18 + tap * 2 + 1) * HWN + p]);
        float m  = __ldg(&mskp[(size_t)(og * 9 + tap) * HWN + p]);
        float fy = (float)(py + (tap / 3) * dil - dil) + dy;
        float fx = (float)(px + (tap % 3) * dil - dil) + dx;
        float y0f = floorf(fy), x0f = floorf(fx);
        float wy = fy - y0f, wx = fx - x0f;
        int y0 = (int)y0f, x0 = (int)x0f;
        float w00 = (1.f - wy) * (1.f - wx) * m;
        float w01 = (1.f - wy) * wx * m;
        float w10 = wy * (1.f - wx) * m;
        float w11 = wy * wx * m;
        bool y0v = (unsigned)y0 < 96u, y1v = (unsigned)(y0 + 1) < 96u;
        bool x0v = (unsigned)x0 < 96u, x1v = (unsigned)(x0 + 1) < 96u;
        float vx = 0.f, vy = 0.f, vz = 0.f, vw = 0.f;
        if (y0v && x0v) {
            float4 t = *(const float4*)&qb[(size_t)(y0 * 96 + x0) * 256 + cb];
            vx += w00 * t.x; vy += w00 * t.y; vz += w00 * t.z; vw += w00 * t.w;
        }
        if (y0v && x1v) {
            float4 t = *(const float4*)&qb[(size_t)(y0 * 96 + x0 + 1) * 256 + cb];
            vx += w01 * t.x; vy += w01 * t.y; vz += w01 * t.z; vw += w01 * t.w;
        }
        if (y1v && x0v) {
            float4 t = *(const float4*)&qb[(size_t)((y0 + 1) * 96 + x0) * 256 + cb];
            vx += w10 * t.x; vy += w10 * t.y; vz += w10 * t.z; vw += w10 * t.w;
        }
        if (y1v && x1v) {
            float4 t = *(const float4*)&qb[(size_t)((y0 + 1) * 96 + x0 + 1) * 256 + cb];
            vx += w11 * t.x; vy += w11 * t.y; vz += w11 * t.z; vw += w11 * t.w;
        }
        {
            float4 w0 = *(const float4*)&wsh[((rbase + 0) * 9 + tap) * 128 + cgrp];
            a0 += vx * w0.x + vy * w0.y + vz * w0.z + vw * w0.w;
        }
        {
            float4 w1 = *(const float4*)&wsh[((rbase + 1) * 9 + tap) * 128 + cgrp];
            a1 += vx * w1.x + vy * w1.y + vz * w1.z + vw * w1.w;
        }
        {
            float4 w2 = *(const float4*)&wsh[((rbase + 2) * 9 + tap) * 128 + cgrp];
            a2 += vx * w2.x + vy * w2.y + vz * w2.z + vw * w2.w;
        }
    }
}

__global__ void deform_kernel() {
    __shared__ __align__(16) float wsh[6 * 9 * 128];
    int z = blockIdx.z;
    int b = z / 3, dz = z - b * 3;
    int dil = 1 << dz;
    int tid = threadIdx.x;
    int lane8 = tid & 7, pl = tid >> 3;
    int px = blockIdx.x * 8 + (pl & 7);
    int py = blockIdx.y * 4 + (pl >> 3);
    int p = py * 96 + px;
    for (int i = tid; i < 6912; i += 256) {
        int r = i / 1152;
        int rem = i - r * 1152;
        int tap = rem >> 7;
        int cg = rem & 127;
        int ex = r >> 1, half = r & 1;
        wsh[i] = g_sW[((size_t)(b * 3 + ex) * 256 + half * 128 + cg) * 9 + tap];
    }
    __syncthreads();
    const float* offp = g_conv + (size_t)(b * NOUT + dz * 216) * HWN;
    const float* mskp = offp + (size_t)144 * HWN;
    const float* qb = g_qhwc + (size_t)b * HWN * CN;
    float a0 = 0.f, a1 = 0.f, a2 = 0.f, a3 = 0.f, a4 = 0.f, a5 = 0.f;
#pragma unroll 1
    for (int og = 0; og < 4; og++)
        deform_og(og, py, px, p, dil, lane8, offp, mskp, qb, wsh, a0, a1, a2, 0);
#pragma unroll 1
    for (int og = 4; og < 8; og++)
        deform_og(og, py, px, p, dil, lane8, offp, mskp, qb, wsh, a3, a4, a5, 3);
    float acc[6] = {a0, a1, a2, a3, a4, a5};
#pragma unroll
    for (int r = 0; r < 6; r++) {
        acc[r] += __shfl_xor_sync(0xffffffffu, acc[r], 1);
        acc[r] += __shfl_xor_sync(0xffffffffu, acc[r], 2);
        acc[r] += __shfl_xor_sync(0xffffffffu, acc[r], 4);
    }
    if (lane8 == 0) {
        size_t obase = ((size_t)b * 24 + 6 + dz * 6) * HWN + p;
#pragma unroll
        for (int r = 0; r < 6; r++) g_sim[obase + (size_t)r * HWN] = acc[r];
    }
}

// ---------------- final 1x1 conv 24 -> 256 ----------------
__global__ void outconv_kernel(const float* __restrict__ ow, const float* __restrict__ ob,
                               float* __restrict__ out) {
    __shared__ float ws[256 * 25];
    __shared__ float st[24 * 65];
    int b = blockIdx.y;
    int m0 = blockIdx.x * 64;
    int tid = threadIdx.x;
    for (int i = tid; i < 6144; i += 256) {
        int oc = i / 24, k = i - oc * 24;
        ws[oc * 25 + k] = ow[i];
    }
    for (int i = tid; i < 24 * 64; i += 256) {
        int ch = i >> 6, j = i & 63;
        st[ch * 65 + j] = g_sim[((size_t)b * 24 + ch) * HWN + m0 + j];
    }
    __syncthreads();
    int j = tid & 63;
    int ocb = (tid >> 6) * 64;
    for (int oc = ocb; oc < ocb + 64; oc++) {
        float a = ob[oc];
#pragma unroll
        for (int k = 0; k < 24; k++) a += ws[oc * 25 + k] * st[k * 65 + j];
        out[((size_t)b * 256 + oc) * HWN + m0 + j] = a;
    }
}

// ---------------- launch ----------------
extern "C" void kernel_launch(void* const* d_in, const int* in_sizes, int n_in,
                              void* d_out, int out_size) {
    const float* qf    = (const float*)d_in[0];
    const float* sf    = (const float*)d_in[1];
    const float* in_w  = (const float*)d_in[2];
    const float* in_b  = (const float*)d_in[3];
    const float* ln_g  = (const float*)d_in[4];
    const float* ln_b  = (const float*)d_in[5];
    const float* out_w = (const float*)d_in[6];
    const float* out_b = (const float*)d_in[7];
    const float* offw1 = (const float*)d_in[8];
    const float* offb1 = (const float*)d_in[9];
    const float* mskw1 = (const float*)d_in[10];
    const float* mskb1 = (const float*)d_in[11];
    const float* offw2 = (const float*)d_in[12];
    const float* offb2 = (const float*)d_in[13];
    const float* mskw2 = (const float*)d_in[14];
    const float* mskb2 = (const float*)d_in[15];
    const float* offw4 = (const float*)d_in[16];
    const float* offb4 = (const float*)d_in[17];
    const float* mskw4 = (const float*)d_in[18];
    const float* mskb4 = (const float*)d_in[19];
    float* out = (float*)d_out;

    pack_wa<<<256, 256>>>(in_w);
    pack_big<<<(KBIG * NPAD + 255) / 256, 256>>>(offw1, mskw1, offw2, mskw2, offw4, mskw4,
                                                 offb1, mskb1, offb2, mskb2, offb4, mskb4);
    gemm_in<<<dim3(72, 4, 2), 256>>>(qf, in_b);
    support_kernel<<<6, 256>>>(sf, in_b, ln_g, ln_b);
    ln_kernel<<<576, 256>>>(ln_g, ln_b);
    gemm_big<<<dim3(72, 11, 2), 256>>>();
    softmax_kernel<<<dim3(36, 3, 2), 256>>>();
    sim0_kernel<<<dim3(288, 2), 256>>>();
    deform_kernel<<<dim3(12, 24, 6), 256>>>();
    outconv_kernel<<<dim3(144, 2), 256>>>(out_w, out_b, out);
}

// round 4
// speedup vs baseline: 2.9682x; 2.9682x over previous
#include <cuda_runtime.h>
#include <cuda_bf16.h>
#include <stdint.h>

#define HWN 9216
#define CN 256
#define BB 2
#define NOUT 648
#define MT 144
#define CH_BIG 36
#define CH_IN 4
#define NT_BIG 6
#define NT_IN 2
#define BLK_ELEMS 16384
#define RS_BIG 768

__device__ __align__(128) __nv_bfloat16 g_Abig[(size_t)MT * CH_BIG * BLK_ELEMS];
__device__ __align__(128) __nv_bfloat16 g_Ain[(size_t)MT * CH_IN * BLK_ELEMS];
__device__ __align__(128) __nv_bfloat16 g_Bbig[(size_t)NT_BIG * CH_BIG * BLK_ELEMS];
__device__ __align__(128) __nv_bfloat16 g_Bin[(size_t)NT_IN * CH_IN * BLK_ELEMS];
__device__ float g_qpre[BB * HWN * CN];
__device__ float g_qhwc[BB * HWN * CN];
__device__ float g_conv2[(size_t)BB * HWN * RS_BIG];
__device__ float g_WA[CN * CN];
__device__ float g_sW[BB * 3 * CN * 9];
__device__ float g_pool[BB * 6 * 128];
__device__ float g_sim[BB * 24 * HWN];
__device__ __align__(16) float g_bpack[768];

__device__ __forceinline__ uint32_t smem_u32(const void* p) {
    uint32_t a;
    asm("{ .reg .u64 t; cvta.to.shared.u64 t, %1; cvt.u32.u64 %0, t; }" : "=r"(a) : "l"(p));
    return a;
}
#define MBINIT(a, c) asm volatile("mbarrier.init.shared.b64 [%0], %1;" ::"r"(a), "r"(c) : "memory")
#define MBEXPECT(a, b) \
    asm volatile("mbarrier.arrive.expect_tx.shared.b64 _, [%0], %1;" ::"r"(a), "r"(b) : "memory")
__device__ __forceinline__ void mbar_wait(uint32_t mbar, uint32_t parity) {
    asm volatile(
        "{\n\t.reg .pred P;\n\t"
        "LAB_%=:\n\t"
        "mbarrier.try_wait.parity.acquire.cta.shared::cta.b64 P, [%0], %1, 0x989680;\n\t"
        "@!P bra LAB_%=;\n\t}" ::"r"(mbar), "r"(parity) : "memory");
}
__device__ __forceinline__ void bulk_g2s(uint32_t dst, const void* src, uint32_t bytes, uint32_t mbar) {
    asm volatile(
        "cp.async.bulk.shared::cluster.global.mbarrier::complete_tx::bytes [%0], [%1], %2, [%3];"
        ::"r"(dst), "l"(src), "r"(bytes), "r"(mbar) : "memory");
}
__device__ __forceinline__ void ldsm4(uint32_t* r, uint32_t addr) {
    asm volatile("ldmatrix.sync.aligned.m8n8.x4.shared.b16 {%0,%1,%2,%3}, [%4];"
                 : "=r"(r[0]), "=r"(r[1]), "=r"(r[2]), "=r"(r[3]) : "r"(addr));
}
__device__ __forceinline__ void mma_bf16(float* c, const uint32_t* a, const uint32_t* b) {
    asm volatile(
        "mma.sync.aligned.m16n8k16.row.col.f32.bf16.bf16.f32 "
        "{%0,%1,%2,%3}, {%4,%5,%6,%7}, {%8,%9}, {%0,%1,%2,%3};"
        : "+f"(c[0]), "+f"(c[1]), "+f"(c[2]), "+f"(c[3])
        : "r"(a[0]), "r"(a[1]), "r"(a[2]), "r"(a[3]), "r"(b[0]), "r"(b[1]));
}

__device__ __forceinline__ void split8(const float* v, __nv_bfloat16* hv, __nv_bfloat16* lv) {
#pragma unroll
    for (int j = 0; j < 8; j++) {
        __nv_bfloat16 h = __float2bfloat16(v[j]);
        hv[j] = h;
        lv[j] = __float2bfloat16(v[j] - __bfloat162float(h));
    }
}

__global__ void pack_wa(const float* __restrict__ inw) {
    int idx = blockIdx.x * 256 + threadIdx.x;
    int k = idx >> 8, n = idx & 255;
    g_WA[k * CN + n] = inw[n * CN + k];
}

__global__ void pack_bias(const float* __restrict__ ob1, const float* __restrict__ mb1,
                          const float* __restrict__ ob2, const float* __restrict__ mb2,
                          const float* __restrict__ ob4, const float* __restrict__ mb4) {
    int idx = blockIdx.x * 256 + threadIdx.x;
    if (idx >= 768) return;
    float v = 0.f;
    if (idx < NOUT) {
        int d = idx / 216, r = idx - d * 216;
        const float* bb = (r < 144) ? (d == 0 ? ob1 : d == 1 ? ob2 : ob4)
                                    : (d == 0 ? mb1 : d == 1 ? mb2 : mb4);
        v = bb[(r < 144) ? r : r - 144];
    }
    g_bpack[idx] = v;
}

__global__ void pack_bin(const float* __restrict__ inw) {
    int nt = blockIdx.x, chunk = blockIdx.y;
    int c0 = chunk * 64;
    char* dst = (char*)(g_Bin + (size_t)(nt * CH_IN + chunk) * BLK_ELEMS);
    int tid = threadIdx.x;
#pragma unroll
    for (int i = 0; i < 4; i++) {
        int unit = i * 256 + tid;
        int r = unit >> 3, u = unit & 7;
        int n = nt * 128 + r;
        float v[8];
#pragma unroll
        for (int j = 0; j < 8; j++) v[j] = inw[(size_t)n * 256 + c0 + u * 8 + j];
        __align__(16) __nv_bfloat16 hv[8], lv[8];
        split8(v, hv, lv);
        uint32_t off = r * 128 + u * 16;
        uint32_t sw = off ^ ((off >> 3) & 0x70);
        *(uint4*)(dst + sw) = *(uint4*)hv;
        *(uint4*)(dst + 16384 + sw) = *(uint4*)lv;
    }
}

__global__ void pack_bbig(const float* __restrict__ ow1, const float* __restrict__ mw1,
                          const float* __restrict__ ow2, const float* __restrict__ mw2,
                          const float* __restrict__ ow4, const float* __restrict__ mw4) {
    int nt = blockIdx.x, chunk = blockIdx.y;
    int tap = chunk >> 2;
    int c0 = (chunk & 3) * 64;
    char* dst = (char*)(g_Bbig + (size_t)(nt * CH_BIG + chunk) * BLK_ELEMS);
    int tid = threadIdx.x;
#pragma unroll
    for (int i = 0; i < 4; i++) {
        int unit = i * 256 + tid;
        int r = unit >> 3, u = unit & 7;
        int n = nt * 128 + r;
        float v[8];
#pragma unroll
        for (int j = 0; j < 8; j++) v[j] = 0.f;
        if (n < NOUT) {
            int d = n / 216, rr = n - d * 216;
            const float* w = (rr < 144) ? (d == 0 ? ow1 : d == 1 ? ow2 : ow4)
                                        : (d == 0 ? mw1 : d == 1 ? mw2 : mw4);
            int oc = (rr < 144) ? rr : rr - 144;
#pragma unroll
            for (int j = 0; j < 8; j++)
                v[j] = w[(size_t)oc * 2304 + (size_t)(c0 + u * 8 + j) * 9 + tap];
        }
        __align__(16) __nv_bfloat16 hv[8], lv[8];
        split8(v, hv, lv);
        uint32_t off = r * 128 + u * 16;
        uint32_t sw = off ^ ((off >> 3) & 0x70);
        *(uint4*)(dst + sw) = *(uint4*)hv;
        *(uint4*)(dst + 16384 + sw) = *(uint4*)lv;
    }
}

__global__ void prep_ain(const float* __restrict__ qf) {
    int mt = blockIdx.x, chunk = blockIdx.y;
    int c0 = chunk * 64;
    char* dst = (char*)(g_Ain + (size_t)(mt * CH_IN + chunk) * BLK_ELEMS);
    int tid = threadIdx.x;
#pragma unroll
    for (int i = 0; i < 4; i++) {
        int unit = i * 256 + tid;
        int r = unit & 127, u = unit >> 7;
        int m = mt * 128 + r;
        int b = m / HWN, p = m - b * HWN;
        float v[8];
#pragma unroll
        for (int j = 0; j < 8; j++) v[j] = qf[((size_t)b * CN + c0 + u * 8 + j) * HWN + p];
        __align__(16) __nv_bfloat16 hv[8], lv[8];
        split8(v, hv, lv);
        uint32_t off = r * 128 + u * 16;
        uint32_t sw = off ^ ((off >> 3) & 0x70);
        *(uint4*)(dst + sw) = *(uint4*)hv;
        *(uint4*)(dst + 16384 + sw) = *(uint4*)lv;
    }
}

__global__ void im2col_big() {
    int mt = blockIdx.x, chunk = blockIdx.y;
    int tap = chunk >> 2;
    int dty = tap / 3 - 1, dtx = tap % 3 - 1;
    int c0 = (chunk & 3) * 64;
    char* dst = (char*)(g_Abig + (size_t)(mt * CH_BIG + chunk) * BLK_ELEMS);
    int tid = threadIdx.x;
#pragma unroll
    for (int i = 0; i < 4; i++) {
        int unit = i * 256 + tid;
        int r = unit >> 3, u = unit & 7;
        int m = mt * 128 + r;
        int b = m / HWN, p = m - b * HWN;
        int y = p / 96, x = p - y * 96;
        int yy = y + dty, xx = x + dtx;
        float v[8];
        if ((unsigned)yy < 96u && (unsigned)xx < 96u) {
            const float* s = g_qhwc + ((size_t)(b * HWN + yy * 96 + xx) * CN + c0 + u * 8);
            float4 a = *(const float4*)s;
            float4 bq = *(const float4*)(s + 4);
            v[0] = a.x; v[1] = a.y; v[2] = a.z; v[3] = a.w;
            v[4] = bq.x; v[5] = bq.y; v[6] = bq.z; v[7] = bq.w;
        } else {
#pragma unroll
            for (int j = 0; j < 8; j++) v[j] = 0.f;
        }
        __align__(16) __nv_bfloat16 hv[8], lv[8];
        split8(v, hv, lv);
        uint32_t off = r * 128 + u * 16;
        uint32_t sw = off ^ ((off >> 3) & 0x70);
        *(uint4*)(dst + sw) = *(uint4*)hv;
        *(uint4*)(dst + 16384 + sw) = *(uint4*)lv;
    }
}

#define STGB 65536
#define SMEM_DYN (1024 + 3 * STGB)

__global__ __launch_bounds__(256, 1) void gemm_mma(int which, const float* __restrict__ bias_in) {
    extern __shared__ char smraw[];
    char* basep = (char*)(((uintptr_t)smraw + 1023) & ~(uintptr_t)1023);
    uint32_t sb = smem_u32(basep);
    const int chunks = which ? CH_BIG : CH_IN;
    const int ntiles = which ? NT_BIG : NT_IN;
    const int rs = which ? RS_BIG : 256;
    const __nv_bfloat16* Ab = which ? g_Abig : g_Ain;
    const __nv_bfloat16* Bb = which ? g_Bbig : g_Bin;
    const float* bias = which ? g_bpack : bias_in;
    float* outp = which ? g_conv2 : g_qpre;
    int mt = blockIdx.x / ntiles, nt = blockIdx.x - (blockIdx.x / ntiles) * ntiles;
    int tid = threadIdx.x, wid = tid >> 5, lane = tid & 31;
    int wm = (wid >> 1) * 32, wn = (wid & 1) * 64;
    uint32_t FULLB = sb, STG = sb + 1024;

    if (tid == 0)
        for (int s = 0; s < 3; s++) MBINIT(FULLB + s * 8, 1);
    __syncthreads();
    const char* Abase = (const char*)(Ab + (size_t)mt * chunks * BLK_ELEMS);
    const char* Bbase = (const char*)(Bb + (size_t)nt * chunks * BLK_ELEMS);
    if (tid == 0) {
        int pre = chunks < 3 ? chunks : 3;
        for (int s = 0; s < pre; s++) {
            MBEXPECT(FULLB + s * 8, 65536u);
            bulk_g2s(STG + s * STGB, Abase + (size_t)s * 32768, 32768u, FULLB + s * 8);
            bulk_g2s(STG + s * STGB + 32768, Bbase + (size_t)s * 32768, 32768u, FULLB + s * 8);
        }
    }

    float acc[2][8][4];
#pragma unroll
    for (int a = 0; a < 2; a++)
#pragma unroll
        for (int b = 0; b < 8; b++)
#pragma unroll
            for (int c = 0; c < 4; c++) acc[a][b][c] = 0.f;

    int x7 = lane & 7;
    int kuA = lane >> 4;
    int kuB = (lane >> 3) & 1;
    uint32_t offA[2], offB[4];
#pragma unroll
    for (int mt2 = 0; mt2 < 2; mt2++)
        offA[mt2] = (uint32_t)(wm + mt2 * 16 + ((lane >> 3) & 1) * 8 + x7) * 128u;
#pragma unroll
    for (int ng = 0; ng < 4; ng++)
        offB[ng] = (uint32_t)(wn + ng * 16 + ((lane >> 4) << 3) + x7) * 128u;

    for (int ch = 0; ch < chunks; ch++) {
        int st = ch % 3;
        mbar_wait(FULLB + st * 8, (uint32_t)((ch / 3) & 1));
        uint32_t aB = STG + st * STGB;
        uint32_t bB = aB + 32768;
#pragma unroll
        for (int ks = 0; ks < 4; ks++) {
            uint32_t cA = (uint32_t)(((ks * 2 + kuA) ^ x7) << 4);
            uint32_t cB = (uint32_t)(((ks * 2 + kuB) ^ x7) << 4);
            uint32_t Ah[2][4], Al[2][4], Bh[4][4], Bl[4][4];
#pragma unroll
            for (int mt2 = 0; mt2 < 2; mt2++) {
                uint32_t ad = aB + offA[mt2] + cA;
                ldsm4(Ah[mt2], ad);
                ldsm4(Al[mt2], ad + 16384);
            }
#pragma unroll
            for (int ng = 0; ng < 4; ng++) {
                uint32_t ad = bB + offB[ng] + cB;
                ldsm4(Bh[ng], ad);
                ldsm4(Bl[ng], ad + 16384);
            }
#pragma unroll
            for (int mt2 = 0; mt2 < 2; mt2++)
#pragma unroll
                for (int n8 = 0; n8 < 8; n8++) {
                    int ng = n8 >> 1, h = (n8 & 1) * 2;
                    mma_bf16(acc[mt2][n8], Ah[mt2], &Bh[ng][h]);
                    mma_bf16(acc[mt2][n8], Ah[mt2], &Bl[ng][h]);
                    mma_bf16(acc[mt2][n8], Al[mt2], &Bh[ng][h]);
                }
        }
        __syncthreads();
        if (tid == 0) {
            int nc = ch + 3;
            if (nc < chunks) {
                MBEXPECT(FULLB + st * 8, 65536u);
                bulk_g2s(STG + st * STGB, Abase + (size_t)nc * 32768, 32768u, FULLB + st * 8);
                bulk_g2s(STG + st * STGB + 32768, Bbase + (size_t)nc * 32768, 32768u, FULLB + st * 8);
            }
        }
    }

#pragma unroll
    for (int mt2 = 0; mt2 < 2; mt2++)
#pragma unroll
        for (int n8 = 0; n8 < 8; n8++) {
            int col = nt * 128 + wn + n8 * 8 + (lane & 3) * 2;
            int row0 = mt * 128 + wm + mt2 * 16 + (lane >> 2);
            float bx = bias[col], by = bias[col + 1];
            float2 v0 = make_float2(acc[mt2][n8][0] + bx, acc[mt2][n8][1] + by);
            float2 v1 = make_float2(acc[mt2][n8][2] + bx, acc[mt2][n8][3] + by);
            *(float2*)&outp[(size_t)row0 * rs + col] = v0;
            *(float2*)&outp[(size_t)(row0 + 8) * rs + col] = v1;
        }
}

__global__ void ln_row(const float* __restrict__ gam, const float* __restrict__ bet) {
    int m = blockIdx.x * 8 + (threadIdx.x >> 5);
    int lane = threadIdx.x & 31;
    const float* src = g_qpre + (size_t)m * 256 + lane * 8;
    float4 a = *(const float4*)src;
    float4 b = *(const float4*)(src + 4);
    float v[8] = {a.x, a.y, a.z, a.w, b.x, b.y, b.z, b.w};
    float s1 = 0.f, s2 = 0.f;
#pragma unroll
    for (int j = 0; j < 8; j++) { s1 += v[j]; s2 += v[j] * v[j]; }
#pragma unroll
    for (int o = 16; o > 0; o >>= 1) {
        s1 += __shfl_xor_sync(0xffffffffu, s1, o);
        s2 += __shfl_xor_sync(0xffffffffu, s2, o);
    }
    float mu = s1 * (1.f / 256.f);
    float rv = rsqrtf(s2 * (1.f / 256.f) - mu * mu + 1e-5f);
    float* dst = g_qhwc + (size_t)m * 256 + lane * 8;
#pragma unroll
    for (int j = 0; j < 8; j++) {
        int c = lane * 8 + j;
        v[j] = (v[j] - mu) * rv * __ldg(&gam[c]) + __ldg(&bet[c]);
    }
    *(float4*)dst = make_float4(v[0], v[1], v[2], v[3]);
    *(float4*)(dst + 4) = make_float4(v[4], v[5], v[6], v[7]);
}

__global__ void support_kernel(const float* __restrict__ sup, const float* __restrict__ inb,
                               const float* __restrict__ gam, const float* __restrict__ bet) {
    __shared__ float xs[2304];
    __shared__ float Wt[32 * 256];
    __shared__ float stats[18];
    int bid = blockIdx.x;
    int b = bid / 3, ex = bid - b * 3;
    int tid = threadIdx.x;
    const float* sp = sup + (size_t)(b * 3 + ex) * 2304;
    for (int i = tid; i < 2304; i += 256) xs[i] = sp[i];
    float acc[9];
    float bia = inb[tid];
#pragma unroll
    for (int pos = 0; pos < 9; pos++) acc[pos] = bia;
    for (int k0 = 0; k0 < 256; k0 += 32) {
        __syncthreads();
        const float4* src = (const float4*)(g_WA + k0 * 256);
        float4* dW = (float4*)Wt;
        for (int i = tid; i < 2048; i += 256) dW[i] = src[i];
        __syncthreads();
#pragma unroll
        for (int kk = 0; kk < 32; kk++) {
            float w = Wt[kk * 256 + tid];
#pragma unroll
            for (int pos = 0; pos < 9; pos++) acc[pos] += w * xs[(k0 + kk) * 9 + pos];
        }
    }
    __syncthreads();
#pragma unroll
    for (int pos = 0; pos < 9; pos++) xs[tid * 9 + pos] = acc[pos];
    __syncthreads();
    if (tid < 9) {
        float s1 = 0.f, s2 = 0.f;
        for (int c = 0; c < 256; c++) { float v = xs[c * 9 + tid]; s1 += v; s2 += v * v; }
        float mu = s1 * (1.f / 256.f);
        stats[tid] = mu;
        stats[9 + tid] = rsqrtf(s2 * (1.f / 256.f) - mu * mu + 1e-5f);
    }
    __syncthreads();
    float mx = -1e30f;
    float g = gam[tid], be = bet[tid];
#pragma unroll
    for (int pos = 0; pos < 9; pos++) {
        float v = (acc[pos] - stats[pos]) * stats[9 + pos] * g + be;
        g_sW[((size_t)(b * 3 + ex) * 256 + tid) * 9 + pos] = v;
        mx = fmaxf(mx, v);
    }
    int r = ex * 2 + (tid >> 7);
    g_pool[(b * 6 + r) * 128 + (tid & 127)] = mx;
}

__global__ void softmax_kernel() {
    int p = blockIdx.x * 256 + threadIdx.x;
    int dz = blockIdx.y, b = blockIdx.z;
    float* base = g_conv2 + ((size_t)(b * HWN) + p) * RS_BIG + dz * 216 + 144;
    float4 e[18];
    float mx = -1e30f;
#pragma unroll
    for (int i = 0; i < 18; i++) {
        e[i] = *(float4*)&base[i * 4];
        mx = fmaxf(mx, fmaxf(fmaxf(e[i].x, e[i].y), fmaxf(e[i].z, e[i].w)));
    }
    float s = 0.f;
#pragma unroll
    for (int i = 0; i < 18; i++) {
        e[i].x = expf(e[i].x - mx); e[i].y = expf(e[i].y - mx);
        e[i].z = expf(e[i].z - mx); e[i].w = expf(e[i].w - mx);
        s += e[i].x + e[i].y + e[i].z + e[i].w;
    }
    float inv = 1.f / s;
#pragma unroll
    for (int i = 0; i < 18; i++) {
        e[i].x *= inv; e[i].y *= inv; e[i].z *= inv; e[i].w *= inv;
        *(float4*)&base[i * 4] = e[i];
    }
}

__global__ void sim0_kernel() {
    __shared__ __align__(16) float psh[6 * 128];
    int b = blockIdx.y;
    int tid = threadIdx.x;
    int lane8 = tid & 7, pl = tid >> 3;
    int pg = blockIdx.x * 32 + pl;
    for (int i = tid; i < 768; i += 256) psh[i] = g_pool[b * 768 + i];
    __syncthreads();
    const float* qrow = g_qhwc + ((size_t)b * HWN + pg) * CN;
    float acc[6];
#pragma unroll
    for (int r = 0; r < 6; r++) acc[r] = 0.f;
#pragma unroll
    for (int r = 0; r < 6; r++) {
        int g = (r >= 3) ? 1 : 0;
#pragma unroll
        for (int qq = 0; qq < 4; qq++) {
            int f = lane8 + qq * 8;
            float4 qv = *(const float4*)&qrow[g * 128 + f * 4];
            float4 pv = *(const float4*)&psh[r * 128 + f * 4];
            acc[r] += qv.x * pv.x + qv.y * pv.y + qv.z * pv.z + qv.w * pv.w;
        }
    }
#pragma unroll
    for (int r = 0; r < 6; r++) {
        acc[r] += __shfl_xor_sync(0xffffffffu, acc[r], 1);
        acc[r] += __shfl_xor_sync(0xffffffffu, acc[r], 2);
        acc[r] += __shfl_xor_sync(0xffffffffu, acc[r], 4);
    }
    if (lane8 == 0)
#pragma unroll
        for (int r = 0; r < 6; r++) g_sim[((size_t)b * 24 + r) * HWN + pg] = acc[r];
}

__device__ __forceinline__ void deform_og(
    int og, int py, int px, int dil, int lane8,
    const float* __restrict__ prow, const float* __restrict__ qb, const float* wsh,
    float& a0, float& a1, float& a2, int rbase) {
    int cb = og * 32 + lane8 * 4;
    int cgrp = (og & 3) * 32 + lane8 * 4;
#pragma unroll
    for (int tap = 0; tap < 9; tap++) {
        float dy = prow[og * 18 + tap * 2];
        float dx = prow[og * 18 + tap * 2 + 1];
        float m = prow[144 + og * 9 + tap];
        float fy = (float)(py + (tap / 3) * dil - dil) + dy;
        float fx = (float)(px + (tap % 3) * dil - dil) + dx;
        float y0f = floorf(fy), x0f = floorf(fx);
        float wy = fy - y0f, wx = fx - x0f;
        int y0 = (int)y0f, x0 = (int)x0f;
        float w00 = (1.f - wy) * (1.f - wx) * m, w01 = (1.f - wy) * wx * m;
        float w10 = wy * (1.f - wx) * m, w11 = wy * wx * m;
        bool y0v = (unsigned)y0 < 96u, y1v = (unsigned)(y0 + 1) < 96u;
        bool x0v = (unsigned)x0 < 96u, x1v = (unsigned)(x0 + 1) < 96u;
        float vx = 0.f, vy = 0.f, vz = 0.f, vw = 0.f;
        if (y0v && x0v) {
            float4 t = *(const float4*)&qb[(size_t)(y0 * 96 + x0) * 256 + cb];
            vx += w00 * t.x; vy += w00 * t.y; vz += w00 * t.z; vw += w00 * t.w;
        }
        if (y0v && x1v) {
            float4 t = *(const float4*)&qb[(size_t)(y0 * 96 + x0 + 1) * 256 + cb];
            vx += w01 * t.x; vy += w01 * t.y; vz += w01 * t.z; vw += w01 * t.w;
        }
        if (y1v && x0v) {
            float4 t = *(const float4*)&qb[(size_t)((y0 + 1) * 96 + x0) * 256 + cb];
            vx += w10 * t.x; vy += w10 * t.y; vz += w10 * t.z; vw += w10 * t.w;
        }
        if (y1v && x1v) {
            float4 t = *(const float4*)&qb[(size_t)((y0 + 1) * 96 + x0 + 1) * 256 + cb];
            vx += w11 * t.x; vy += w11 * t.y; vz += w11 * t.z; vw += w11 * t.w;
        }
        float4 w0 = *(const float4*)&wsh[((rbase + 0) * 9 + tap) * 128 + cgrp];
        a0 += vx * w0.x + vy * w0.y + vz * w0.z + vw * w0.w;
        float4 w1 = *(const float4*)&wsh[((rbase + 1) * 9 + tap) * 128 + cgrp];
        a1 += vx * w1.x + vy * w1.y + vz * w1.z + vw * w1.w;
        float4 w2 = *(const float4*)&wsh[((rbase + 2) * 9 + tap) * 128 + cgrp];
        a2 += vx * w2.x + vy * w2.y + vz * w2.z + vw * w2.w;
    }
}

__global__ void deform_kernel() {
    __shared__ __align__(16) float wsh[6 * 9 * 128];
    int z = blockIdx.z;
    int b = z / 3, dz = z - b * 3;
    int dil = 1 << dz;
    int tid = threadIdx.x;
    int lane8 = tid & 7, pl = tid >> 3;
    int px = blockIdx.x * 8 + (pl & 7);
    int py = blockIdx.y * 4 + (pl >> 3);
    int p = py * 96 + px;
    for (int i = tid; i < 6912; i += 256) {
        int r = i / 1152;
        int rem = i - r * 1152;
        int tap = rem >> 7;
        int cg = rem & 127;
        int ex = r >> 1, half = r & 1;
        wsh[i] = g_sW[((size_t)(b * 3 + ex) * 256 + half * 128 + cg) * 9 + tap];
    }
    __syncthreads();
    const float* prow = g_conv2 + ((size_t)(b * HWN) + p) * RS_BIG + dz * 216;
    const float* qb = g_qhwc + (size_t)b * HWN * CN;
    float a0 = 0.f, a1 = 0.f, a2 = 0.f, a3 = 0.f, a4 = 0.f, a5 = 0.f;
#pragma unroll 1
    for (int og = 0; og < 4; og++) deform_og(og, py, px, dil, lane8, prow, qb, wsh, a0, a1, a2, 0);
#pragma unroll 1
    for (int og = 4; og < 8; og++) deform_og(og, py, px, dil, lane8, prow, qb, wsh, a3, a4, a5, 3);
    float acc[6] = {a0, a1, a2, a3, a4, a5};
#pragma unroll
    for (int r = 0; r < 6; r++) {
        acc[r] += __shfl_xor_sync(0xffffffffu, acc[r], 1);
        acc[r] += __shfl_xor_sync(0xffffffffu, acc[r], 2);
        acc[r] += __shfl_xor_sync(0xffffffffu, acc[r], 4);
    }
    if (lane8 == 0) {
        size_t obase = ((size_t)b * 24 + 6 + dz * 6) * HWN + p;
#pragma unroll
        for (int r = 0; r < 6; r++) g_sim[obase + (size_t)r * HWN] = acc[r];
    }
}

__global__ void outconv_kernel(const float* __restrict__ ow, const float* __restrict__ ob,
                               float* __restrict__ out) {
    __shared__ float ws[256 * 25];
    __shared__ float st[24 * 65];
    int b = blockIdx.y;
    int m0 = blockIdx.x * 64;
    int tid = threadIdx.x;
    for (int i = tid; i < 6144; i += 256) {
        int oc = i / 24, k = i - oc * 24;
        ws[oc * 25 + k] = ow[i];
    }
    for (int i = tid; i < 24 * 64; i += 256) {
        int ch = i >> 6, j = i & 63;
        st[ch * 65 + j] = g_sim[((size_t)b * 24 + ch) * HWN + m0 + j];
    }
    __syncthreads();
    int j = tid & 63;
    int ocb = (tid >> 6) * 64;
    for (int oc = ocb; oc < ocb + 64; oc++) {
        float a = ob[oc];
#pragma unroll
        for (int k = 0; k < 24; k++) a += ws[oc * 25 + k] * st[k * 65 + j];
        out[((size_t)b * 256 + oc) * HWN + m0 + j] = a;
    }
}

extern "C" void kernel_launch(void* const* d_in, const int* in_sizes, int n_in,
                              void* d_out, int out_size) {
    const float* qf = (const float*)d_in[0];
    const float* sf = (const float*)d_in[1];
    const float* in_w = (const float*)d_in[2];
    const float* in_b = (const float*)d_in[3];
    const float* ln_g = (const float*)d_in[4];
    const float* ln_b = (const float*)d_in[5];
    const float* out_w = (const float*)d_in[6];
    const float* out_b = (const float*)d_in[7];
    const float* offw1 = (const float*)d_in[8];
    const float* offb1 = (const float*)d_in[9];
    const float* mskw1 = (const float*)d_in[10];
    const float* mskb1 = (const float*)d_in[11];
    const float* offw2 = (const float*)d_in[12];
    const float* offb2 = (const float*)d_in[13];
    const float* mskw2 = (const float*)d_in[14];
    const float* mskb2 = (const float*)d_in[15];
    const float* offw4 = (const float*)d_in[16];
    const float* offb4 = (const float*)d_in[17];
    const float* mskw4 = (const float*)d_in[18];
    const float* mskb4 = (const float*)d_in[19];
    float* out = (float*)d_out;

    cudaFuncSetAttribute(gemm_mma, cudaFuncAttributeMaxDynamicSharedMemorySize, SMEM_DYN);

    pack_wa<<<256, 256>>>(in_w);
    pack_bias<<<3, 256>>>(offb1, mskb1, offb2, mskb2, offb4, mskb4);
    pack_bin<<<dim3(NT_IN, CH_IN), 256>>>(in_w);
    pack_bbig<<<dim3(NT_BIG, CH_BIG), 256>>>(offw1, mskw1, offw2, mskw2, offw4, mskw4);
    prep_ain<<<dim3(MT, CH_IN), 256>>>(qf);
    gemm_mma<<<MT * NT_IN, 256, SMEM_DYN>>>(0, in_b);
    support_kernel<<<6, 256>>>(sf, in_b, ln_g, ln_b);
    ln_row<<<2304, 256>>>(ln_g, ln_b);
    im2col_big<<<dim3(MT, CH_BIG), 256>>>();
    gemm_mma<<<MT * NT_BIG, 256, SMEM_DYN>>>(1, nullptr);
    softmax_kernel<<<dim3(36, 3, 2), 256>>>();
    sim0_kernel<<<dim3(288, 2), 256>>>();
    deform_kernel<<<dim3(12, 24, 6), 256>>>();
    outconv_kernel<<<dim3(144, 2), 256>>>(out_w, out_b, out);
}

// round 5
// speedup vs baseline: 3.0393x; 1.0240x over previous
#include <cuda_runtime.h>
#include <cuda_bf16.h>
#include <stdint.h>

#define HWN 9216
#define CN 256
#define BB 2
#define NOUT 648
#define CH_BIG 36
#define CH_IN 4
#define NT_BIG 3
#define MT_IN 144
#define BTILES 75
#define MT_BIG (BB * BTILES)
#define PADW 98
#define PROWS 9856           // 128 + 75*128 + 128 per batch
#define QROWS 19712          // 2 * PROWS
#define RS_BIG 768

// packed bf16 tiles
__device__ __align__(128) __nv_bfloat16 g_qpad[(size_t)8 * QROWS * 64];   // [cq*2+half][row][64]
__device__ __align__(128) __nv_bfloat16 g_Ain[(size_t)MT_IN * CH_IN * 16384];
__device__ __align__(128) __nv_bfloat16 g_Bbig[(size_t)NT_BIG * CH_BIG * 32768];
__device__ __align__(128) __nv_bfloat16 g_Bin[(size_t)CH_IN * 32768];
__device__ float g_qpre[BB * HWN * CN];
__device__ float g_qhwc[BB * HWN * CN];
__device__ float g_conv2[(size_t)BB * HWN * RS_BIG];
__device__ float g_WA[CN * CN];
__device__ float g_sW[BB * 3 * CN * 9];
__device__ float g_pool[BB * 6 * 128];
__device__ float g_sim[BB * 24 * HWN];
__device__ __align__(16) float g_bpack[768];

__device__ __forceinline__ uint32_t smem_u32(const void* p) {
    uint32_t a;
    asm("{ .reg .u64 t; cvta.to.shared.u64 t, %1; cvt.u32.u64 %0, t; }" : "=r"(a) : "l"(p));
    return a;
}
#define MBINIT(a, c) asm volatile("mbarrier.init.shared.b64 [%0], %1;" ::"r"(a), "r"(c) : "memory")
#define MBEXPECT(a, b) \
    asm volatile("mbarrier.arrive.expect_tx.shared.b64 _, [%0], %1;" ::"r"(a), "r"(b) : "memory")
__device__ __forceinline__ void mbar_wait(uint32_t mbar, uint32_t parity) {
    asm volatile(
        "{\n\t.reg .pred P;\n\t"
        "LAB_%=:\n\t"
        "mbarrier.try_wait.parity.acquire.cta.shared::cta.b64 P, [%0], %1, 0x989680;\n\t"
        "@!P bra LAB_%=;\n\t}" ::"r"(mbar), "r"(parity) : "memory");
}
__device__ __forceinline__ void bulk_g2s(uint32_t dst, const void* src, uint32_t bytes, uint32_t mbar) {
    asm volatile(
        "cp.async.bulk.shared::cluster.global.mbarrier::complete_tx::bytes [%0], [%1], %2, [%3];"
        ::"r"(dst), "l"(src), "r"(bytes), "r"(mbar) : "memory");
}
__device__ __forceinline__ void ldsm4(uint32_t* r, uint32_t addr) {
    asm volatile("ldmatrix.sync.aligned.m8n8.x4.shared.b16 {%0,%1,%2,%3}, [%4];"
                 : "=r"(r[0]), "=r"(r[1]), "=r"(r[2]), "=r"(r[3]) : "r"(addr));
}
__device__ __forceinline__ void mma_bf16(float* c, const uint32_t* a, const uint32_t* b) {
    asm volatile(
        "mma.sync.aligned.m16n8k16.row.col.f32.bf16.bf16.f32 "
        "{%0,%1,%2,%3}, {%4,%5,%6,%7}, {%8,%9}, {%0,%1,%2,%3};"
        : "+f"(c[0]), "+f"(c[1]), "+f"(c[2]), "+f"(c[3])
        : "r"(a[0]), "r"(a[1]), "r"(a[2]), "r"(a[3]), "r"(b[0]), "r"(b[1]));
}
__device__ __forceinline__ void split8(const float* v, __nv_bfloat16* hv, __nv_bfloat16* lv) {
#pragma unroll
    for (int j = 0; j < 8; j++) {
        __nv_bfloat16 h = __float2bfloat16(v[j]);
        hv[j] = h;
        lv[j] = __float2bfloat16(v[j] - __bfloat162float(h));
    }
}

__global__ void pack_wa(const float* __restrict__ inw) {
    int idx = blockIdx.x * 256 + threadIdx.x;
    int k = idx >> 8, n = idx & 255;
    g_WA[k * CN + n] = inw[n * CN + k];
}

__global__ void pack_bias(const float* __restrict__ ob1, const float* __restrict__ mb1,
                          const float* __restrict__ ob2, const float* __restrict__ mb2,
                          const float* __restrict__ ob4, const float* __restrict__ mb4) {
    int idx = blockIdx.x * 256 + threadIdx.x;
    if (idx >= 768) return;
    float v = 0.f;
    if (idx < NOUT) {
        int d = idx / 216, r = idx - d * 216;
        const float* bb = (r < 144) ? (d == 0 ? ob1 : d == 1 ? ob2 : ob4)
                                    : (d == 0 ? mb1 : d == 1 ? mb2 : mb4);
        v = bb[(r < 144) ? r : r - 144];
    }
    g_bpack[idx] = v;
}

// B for in-projection: N=256 rows, 64KB block per chunk (hi 32K + lo 32K)
__global__ void pack_bin(const float* __restrict__ inw) {
    int chunk = blockIdx.x;
    int c0 = chunk * 64;
    char* dst = (char*)(g_Bin + (size_t)chunk * 32768);
    int tid = threadIdx.x;
#pragma unroll
    for (int i = 0; i < 8; i++) {
        int unit = i * 256 + tid;
        int r = unit >> 3, u = unit & 7;
        float v[8];
#pragma unroll
        for (int j = 0; j < 8; j++) v[j] = inw[(size_t)r * 256 + c0 + u * 8 + j];
        __align__(16) __nv_bfloat16 hv[8], lv[8];
        split8(v, hv, lv);
        uint32_t off = r * 128 + u * 16;
        uint32_t sw = off ^ ((off >> 3) & 0x70);
        *(uint4*)(dst + sw) = *(uint4*)hv;
        *(uint4*)(dst + 32768 + sw) = *(uint4*)lv;
    }
}

// B for big conv: 3 n-tiles of 256 rows, 64KB blocks
__global__ void pack_bbig(const float* __restrict__ ow1, const float* __restrict__ mw1,
                          const float* __restrict__ ow2, const float* __restrict__ mw2,
                          const float* __restrict__ ow4, const float* __restrict__ mw4) {
    int nt = blockIdx.x, chunk = blockIdx.y;
    int tap = chunk >> 2;
    int c0 = (chunk & 3) * 64;
    char* dst = (char*)(g_Bbig + (size_t)(nt * CH_BIG + chunk) * 32768);
    int tid = threadIdx.x;
#pragma unroll
    for (int i = 0; i < 8; i++) {
        int unit = i * 256 + tid;
        int r = unit >> 3, u = unit & 7;
        int n = nt * 256 + r;
        float v[8];
#pragma unroll
        for (int j = 0; j < 8; j++) v[j] = 0.f;
        if (n < NOUT) {
            int d = n / 216, rr = n - d * 216;
            const float* w = (rr < 144) ? (d == 0 ? ow1 : d == 1 ? ow2 : ow4)
                                        : (d == 0 ? mw1 : d == 1 ? mw2 : mw4);
            int oc = (rr < 144) ? rr : rr - 144;
#pragma unroll
            for (int j = 0; j < 8; j++)
                v[j] = w[(size_t)oc * 2304 + (size_t)(c0 + u * 8 + j) * 9 + tap];
        }
        __align__(16) __nv_bfloat16 hv[8], lv[8];
        split8(v, hv, lv);
        uint32_t off = r * 128 + u * 16;
        uint32_t sw = off ^ ((off >> 3) & 0x70);
        *(uint4*)(dst + sw) = *(uint4*)hv;
        *(uint4*)(dst + 32768 + sw) = *(uint4*)lv;
    }
}

__global__ void prep_ain(const float* __restrict__ qf) {
    int mt = blockIdx.x, chunk = blockIdx.y;
    int c0 = chunk * 64;
    char* dst = (char*)(g_Ain + (size_t)(mt * CH_IN + chunk) * 16384);
    int tid = threadIdx.x;
#pragma unroll
    for (int i = 0; i < 4; i++) {
        int unit = i * 256 + tid;
        int r = unit & 127, u = unit >> 7;
        int m = mt * 128 + r;
        int b = m / HWN, p = m - b * HWN;
        float v[8];
#pragma unroll
        for (int j = 0; j < 8; j++) v[j] = qf[((size_t)b * CN + c0 + u * 8 + j) * HWN + p];
        __align__(16) __nv_bfloat16 hv[8], lv[8];
        split8(v, hv, lv);
        uint32_t off = r * 128 + u * 16;
        uint32_t sw = off ^ ((off >> 3) & 0x70);
        *(uint4*)(dst + sw) = *(uint4*)hv;
        *(uint4*)(dst + 16384 + sw) = *(uint4*)lv;
    }
}

#define STGB 98304
#define SMEM_DYN (1024 + 2 * STGB)

__global__ __launch_bounds__(256, 1) void gemm_mma(int which, const float* __restrict__ bias_in) {
    extern __shared__ char smraw[];
    char* basep = (char*)(((uintptr_t)smraw + 1023) & ~(uintptr_t)1023);
    uint32_t sb = smem_u32(basep);
    const int chunks = which ? CH_BIG : CH_IN;
    const int ntiles = which ? NT_BIG : 1;
    const float* bias = which ? g_bpack : bias_in;
    int bx = blockIdx.x;
    int mt = bx / ntiles, nt = bx - (bx / ntiles) * ntiles;
    int b = 0, mt_local = mt;
    size_t arowbase = 0;
    if (which) {
        b = mt / BTILES;
        mt_local = mt - b * BTILES;
        arowbase = (size_t)b * PROWS + 128 + (size_t)mt_local * 128;
    }
    int tid = threadIdx.x, wid = tid >> 5, lane = tid & 31;
    int wm = (wid & 3) * 32, wn = (wid >> 2) * 128;
    uint32_t FULLB = sb, STG = sb + 1024;

    if (tid == 0)
        for (int s = 0; s < 2; s++) MBINIT(FULLB + s * 8, 1);
    __syncthreads();

    auto issue = [&](int ch, int st) {
        uint32_t S = STG + st * STGB;
        MBEXPECT(FULLB + st * 8, 98304u);
        if (which) {
            int tap = ch >> 2, cq = ch & 3;
            int shift = (tap / 3 - 1) * PADW + (tap % 3 - 1);
            size_t row0 = arowbase + shift;
            bulk_g2s(S, g_qpad + ((size_t)(cq * 2) * QROWS + row0) * 64, 16384u, FULLB + st * 8);
            bulk_g2s(S + 16384, g_qpad + ((size_t)(cq * 2 + 1) * QROWS + row0) * 64, 16384u,
                     FULLB + st * 8);
            bulk_g2s(S + 32768, g_Bbig + (size_t)(nt * CH_BIG + ch) * 32768, 65536u, FULLB + st * 8);
        } else {
            bulk_g2s(S, g_Ain + (size_t)(mt * CH_IN + ch) * 16384, 32768u, FULLB + st * 8);
            bulk_g2s(S + 32768, g_Bin + (size_t)ch * 32768, 65536u, FULLB + st * 8);
        }
    };
    if (tid == 0) { issue(0, 0); issue(1, 1); }

    float acc[2][16][4];
#pragma unroll
    for (int a = 0; a < 2; a++)
#pragma unroll
        for (int n = 0; n < 16; n++)
#pragma unroll
            for (int c = 0; c < 4; c++) acc[a][n][c] = 0.f;

    int x7 = lane & 7;
    int kuA = lane >> 4;
    int kuB = (lane >> 3) & 1;
    uint32_t offA[2], offB[8];
#pragma unroll
    for (int mt2 = 0; mt2 < 2; mt2++)
        offA[mt2] = (uint32_t)(wm + mt2 * 16 + ((lane >> 3) & 1) * 8 + x7) * 128u;
#pragma unroll
    for (int ng = 0; ng < 8; ng++)
        offB[ng] = (uint32_t)(wn + ng * 16 + ((lane >> 4) << 3) + x7) * 128u;

    for (int ch = 0; ch < chunks; ch++) {
        int st = ch & 1;
        mbar_wait(FULLB + st * 8, (uint32_t)((ch >> 1) & 1));
        uint32_t aB = STG + st * STGB;
        uint32_t bB = aB + 32768;
        int xA = x7;
        if (which) {
            int tap = ch >> 2;
            int shift = (tap / 3 - 1) * PADW + (tap % 3 - 1);
            xA = (x7 + shift) & 7;
        }
#pragma unroll
        for (int ks = 0; ks < 4; ks++) {
            uint32_t cA = (uint32_t)(((ks * 2 + kuA) ^ xA) << 4);
            uint32_t cB = (uint32_t)(((ks * 2 + kuB) ^ x7) << 4);
            uint32_t Ah[2][4], Al[2][4];
#pragma unroll
            for (int mt2 = 0; mt2 < 2; mt2++) {
                uint32_t ad = aB + offA[mt2] + cA;
                ldsm4(Ah[mt2], ad);
                ldsm4(Al[mt2], ad + 16384);
            }
#pragma unroll
            for (int ng = 0; ng < 8; ng++) {
                uint32_t Bh[4], Bl[4];
                uint32_t ad = bB + offB[ng] + cB;
                ldsm4(Bh, ad);
                ldsm4(Bl, ad + 32768);
#pragma unroll
                for (int h = 0; h < 2; h++) {
                    int n8 = ng * 2 + h;
#pragma unroll
                    for (int mt2 = 0; mt2 < 2; mt2++) {
                        mma_bf16(acc[mt2][n8], Ah[mt2], &Bh[h * 2]);
                        mma_bf16(acc[mt2][n8], Ah[mt2], &Bl[h * 2]);
                        mma_bf16(acc[mt2][n8], Al[mt2], &Bh[h * 2]);
                    }
                }
            }
        }
        __syncthreads();
        if (tid == 0 && ch + 2 < chunks) issue(ch + 2, st);
    }

    // epilogue
    if (which) {
#pragma unroll
        for (int mt2 = 0; mt2 < 2; mt2++) {
#pragma unroll
            for (int half = 0; half < 2; half++) {
                int r = wm + mt2 * 16 + (lane >> 2) + half * 8;
                int pp = mt_local * 128 + r;
                int yq = pp / PADW, xq = pp - yq * PADW;
                bool ok = (yq >= 1) && (yq <= 96) && (xq >= 1) && (xq <= 96);
                if (!ok) continue;
                float* drow = g_conv2 + ((size_t)(b * HWN + (yq - 1) * 96 + xq - 1)) * RS_BIG;
#pragma unroll
                for (int n8 = 0; n8 < 16; n8++) {
                    int col = nt * 256 + wn + n8 * 8 + (lane & 3) * 2;
                    float2 v = make_float2(acc[mt2][n8][half * 2 + 0] + bias[col],
                                           acc[mt2][n8][half * 2 + 1] + bias[col + 1]);
                    *(float2*)&drow[col] = v;
                }
            }
        }
    } else {
#pragma unroll
        for (int mt2 = 0; mt2 < 2; mt2++) {
#pragma unroll
            for (int half = 0; half < 2; half++) {
                int r = wm + mt2 * 16 + (lane >> 2) + half * 8;
                float* drow = g_qpre + (size_t)(mt * 128 + r) * 256;
#pragma unroll
                for (int n8 = 0; n8 < 16; n8++) {
                    int col = wn + n8 * 8 + (lane & 3) * 2;
                    float2 v = make_float2(acc[mt2][n8][half * 2 + 0] + bias[col],
                                           acc[mt2][n8][half * 2 + 1] + bias[col + 1]);
                    *(float2*)&drow[col] = v;
                }
            }
        }
    }
}

// LayerNorm + write fp32 HWC + packed/swizzled bf16 hi/lo into padded qpad
__global__ void ln_row(const float* __restrict__ gam, const float* __restrict__ bet) {
    int m = blockIdx.x * 8 + (threadIdx.x >> 5);
    int lane = threadIdx.x & 31;
    const float* src = g_qpre + (size_t)m * 256 + lane * 8;
    float4 a = *(const float4*)src;
    float4 b4 = *(const float4*)(src + 4);
    float v[8] = {a.x, a.y, a.z, a.w, b4.x, b4.y, b4.z, b4.w};
    float s1 = 0.f, s2 = 0.f;
#pragma unroll
    for (int j = 0; j < 8; j++) { s1 += v[j]; s2 += v[j] * v[j]; }
#pragma unroll
    for (int o = 16; o > 0; o >>= 1) {
        s1 += __shfl_xor_sync(0xffffffffu, s1, o);
        s2 += __shfl_xor_sync(0xffffffffu, s2, o);
    }
    float mu = s1 * (1.f / 256.f);
    float rv = rsqrtf(s2 * (1.f / 256.f) - mu * mu + 1e-5f);
#pragma unroll
    for (int j = 0; j < 8; j++) {
        int c = lane * 8 + j;
        v[j] = (v[j] - mu) * rv * __ldg(&gam[c]) + __ldg(&bet[c]);
    }
    float* dst = g_qhwc + (size_t)m * 256 + lane * 8;
    *(float4*)dst = make_float4(v[0], v[1], v[2], v[3]);
    *(float4*)(dst + 4) = make_float4(v[4], v[5], v[6], v[7]);
    // qpad write
    int b = m / HWN, p = m - b * HWN;
    int y = p / 96, x = p - y * 96;
    size_t r_abs = (size_t)b * PROWS + 128 + (size_t)(y + 1) * PADW + (x + 1);
    int cq = lane >> 3, u = lane & 7;
    uint32_t sw = (uint32_t)(u * 16) ^ (((uint32_t)r_abs & 7) << 4);
    __align__(16) __nv_bfloat16 hv[8], lv[8];
    split8(v, hv, lv);
    char* hb = (char*)(g_qpad + ((size_t)(cq * 2) * QROWS + r_abs) * 64);
    char* lb = (char*)(g_qpad + ((size_t)(cq * 2 + 1) * QROWS + r_abs) * 64);
    *(uint4*)(hb + sw) = *(uint4*)hv;
    *(uint4*)(lb + sw) = *(uint4*)lv;
}

__global__ void support_kernel(const float* __restrict__ sup, const float* __restrict__ inb,
                               const float* __restrict__ gam, const float* __restrict__ bet) {
    __shared__ float xs[2304];
    __shared__ float Wt[32 * 256];
    __shared__ float stats[18];
    int bid = blockIdx.x;
    int b = bid / 3, ex = bid - b * 3;
    int tid = threadIdx.x;
    const float* sp = sup + (size_t)(b * 3 + ex) * 2304;
    for (int i = tid; i < 2304; i += 256) xs[i] = sp[i];
    float acc[9];
    float bia = inb[tid];
#pragma unroll
    for (int pos = 0; pos < 9; pos++) acc[pos] = bia;
    for (int k0 = 0; k0 < 256; k0 += 32) {
        __syncthreads();
        const float4* src = (const float4*)(g_WA + k0 * 256);
        float4* dW = (float4*)Wt;
        for (int i = tid; i < 2048; i += 256) dW[i] = src[i];
        __syncthreads();
#pragma unroll
        for (int kk = 0; kk < 32; kk++) {
            float w = Wt[kk * 256 + tid];
#pragma unroll
            for (int pos = 0; pos < 9; pos++) acc[pos] += w * xs[(k0 + kk) * 9 + pos];
        }
    }
    __syncthreads();
#pragma unroll
    for (int pos = 0; pos < 9; pos++) xs[tid * 9 + pos] = acc[pos];
    __syncthreads();
    if (tid < 9) {
        float s1 = 0.f, s2 = 0.f;
        for (int c = 0; c < 256; c++) { float v = xs[c * 9 + tid]; s1 += v; s2 += v * v; }
        float mu = s1 * (1.f / 256.f);
        stats[tid] = mu;
        stats[9 + tid] = rsqrtf(s2 * (1.f / 256.f) - mu * mu + 1e-5f);
    }
    __syncthreads();
    float mx = -1e30f;
    float g = gam[tid], be = bet[tid];
#pragma unroll
    for (int pos = 0; pos < 9; pos++) {
        float v = (acc[pos] - stats[pos]) * stats[9 + pos] * g + be;
        g_sW[((size_t)(b * 3 + ex) * 256 + tid) * 9 + pos] = v;
        mx = fmaxf(mx, v);
    }
    int r = ex * 2 + (tid >> 7);
    g_pool[(b * 6 + r) * 128 + (tid & 127)] = mx;
}

__global__ void softmax_kernel() {
    int p = blockIdx.x * 256 + threadIdx.x;
    int dz = blockIdx.y, b = blockIdx.z;
    float* base = g_conv2 + ((size_t)(b * HWN) + p) * RS_BIG + dz * 216 + 144;
    float4 e[18];
    float mx = -1e30f;
#pragma unroll
    for (int i = 0; i < 18; i++) {
        e[i] = *(float4*)&base[i * 4];
        mx = fmaxf(mx, fmaxf(fmaxf(e[i].x, e[i].y), fmaxf(e[i].z, e[i].w)));
    }
    float s = 0.f;
#pragma unroll
    for (int i = 0; i < 18; i++) {
        e[i].x = expf(e[i].x - mx); e[i].y = expf(e[i].y - mx);
        e[i].z = expf(e[i].z - mx); e[i].w = expf(e[i].w - mx);
        s += e[i].x + e[i].y + e[i].z + e[i].w;
    }
    float inv = 1.f / s;
#pragma unroll
    for (int i = 0; i < 18; i++) {
        e[i].x *= inv; e[i].y *= inv; e[i].z *= inv; e[i].w *= inv;
        *(float4*)&base[i * 4] = e[i];
    }
}

__global__ void sim0_kernel() {
    __shared__ __align__(16) float psh[6 * 128];
    int b = blockIdx.y;
    int tid = threadIdx.x;
    int lane8 = tid & 7, pl = tid >> 3;
    int pg = blockIdx.x * 32 + pl;
    for (int i = tid; i < 768; i += 256) psh[i] = g_pool[b * 768 + i];
    __syncthreads();
    const float* qrow = g_qhwc + ((size_t)b * HWN + pg) * CN;
    float acc[6];
#pragma unroll
    for (int r = 0; r < 6; r++) acc[r] = 0.f;
#pragma unroll
    for (int r = 0; r < 6; r++) {
        int g = (r >= 3) ? 1 : 0;
#pragma unroll
        for (int qq = 0; qq < 4; qq++) {
            int f = lane8 + qq * 8;
            float4 qv = *(const float4*)&qrow[g * 128 + f * 4];
            float4 pv = *(const float4*)&psh[r * 128 + f * 4];
            acc[r] += qv.x * pv.x + qv.y * pv.y + qv.z * pv.z + qv.w * pv.w;
        }
    }
#pragma unroll
    for (int r = 0; r < 6; r++) {
        acc[r] += __shfl_xor_sync(0xffffffffu, acc[r], 1);
        acc[r] += __shfl_xor_sync(0xffffffffu, acc[r], 2);
        acc[r] += __shfl_xor_sync(0xffffffffu, acc[r], 4);
    }
    if (lane8 == 0)
#pragma unroll
        for (int r = 0; r < 6; r++) g_sim[((size_t)b * 24 + r) * HWN + pg] = acc[r];
}

__device__ __forceinline__ void deform_og(
    int og, int py, int px, int dil, int lane8,
    const float* __restrict__ prow, const float* __restrict__ qb, const float* wsh,
    float& a0, float& a1, float& a2, int rbase) {
    int cb = og * 32 + lane8 * 4;
    int cgrp = (og & 3) * 32 + lane8 * 4;
#pragma unroll
    for (int tap = 0; tap < 9; tap++) {
        float dy = prow[og * 18 + tap * 2];
        float dx = prow[og * 18 + tap * 2 + 1];
        float m = prow[144 + og * 9 + tap];
        float fy = (float)(py + (tap / 3) * dil - dil) + dy;
        float fx = (float)(px + (tap % 3) * dil - dil) + dx;
        float y0f = floorf(fy), x0f = floorf(fx);
        float wy = fy - y0f, wx = fx - x0f;
        int y0 = (int)y0f, x0 = (int)x0f;
        float w00 = (1.f - wy) * (1.f - wx) * m, w01 = (1.f - wy) * wx * m;
        float w10 = wy * (1.f - wx) * m, w11 = wy * wx * m;
        bool y0v = (unsigned)y0 < 96u, y1v = (unsigned)(y0 + 1) < 96u;
        bool x0v = (unsigned)x0 < 96u, x1v = (unsigned)(x0 + 1) < 96u;
        float vx = 0.f, vy = 0.f, vz = 0.f, vw = 0.f;
        if (y0v && x0v) {
            float4 t = *(const float4*)&qb[(size_t)(y0 * 96 + x0) * 256 + cb];
            vx += w00 * t.x; vy += w00 * t.y; vz += w00 * t.z; vw += w00 * t.w;
        }
        if (y0v && x1v) {
            float4 t = *(const float4*)&qb[(size_t)(y0 * 96 + x0 + 1) * 256 + cb];
            vx += w01 * t.x; vy += w01 * t.y; vz += w01 * t.z; vw += w01 * t.w;
        }
        if (y1v && x0v) {
            float4 t = *(const float4*)&qb[(size_t)((y0 + 1) * 96 + x0) * 256 + cb];
            vx += w10 * t.x; vy += w10 * t.y; vz += w10 * t.z; vw += w10 * t.w;
        }
        if (y1v && x1v) {
            float4 t = *(const float4*)&qb[(size_t)((y0 + 1) * 96 + x0 + 1) * 256 + cb];
            vx += w11 * t.x; vy += w11 * t.y; vz += w11 * t.z; vw += w11 * t.w;
        }
        float4 w0 = *(const float4*)&wsh[((rbase + 0) * 9 + tap) * 128 + cgrp];
        a0 += vx * w0.x + vy * w0.y + vz * w0.z + vw * w0.w;
        float4 w1 = *(const float4*)&wsh[((rbase + 1) * 9 + tap) * 128 + cgrp];
        a1 += vx * w1.x + vy * w1.y + vz * w1.z + vw * w1.w;
        float4 w2 = *(const float4*)&wsh[((rbase + 2) * 9 + tap) * 128 + cgrp];
        a2 += vx * w2.x + vy * w2.y + vz * w2.z + vw * w2.w;
    }
}

__global__ void deform_kernel() {
    __shared__ __align__(16) float wsh[6 * 9 * 128];
    int z = blockIdx.z;
    int b = z / 3, dz = z - b * 3;
    int dil = 1 << dz;
    int tid = threadIdx.x;
    int lane8 = tid & 7, pl = tid >> 3;
    int px = blockIdx.x * 8 + (pl & 7);
    int py = blockIdx.y * 4 + (pl >> 3);
    int p = py * 96 + px;
    for (int i = tid; i < 6912; i += 256) {
        int r = i / 1152;
        int rem = i - r * 1152;
        int tap = rem >> 7;
        int cg = rem & 127;
        int ex = r >> 1, half = r & 1;
        wsh[i] = g_sW[((size_t)(b * 3 + ex) * 256 + half * 128 + cg) * 9 + tap];
    }
    __syncthreads();
    const float* prow = g_conv2 + ((size_t)(b * HWN) + p) * RS_BIG + dz * 216;
    const float* qb = g_qhwc + (size_t)b * HWN * CN;
    float a0 = 0.f, a1 = 0.f, a2 = 0.f, a3 = 0.f, a4 = 0.f, a5 = 0.f;
#pragma unroll 1
    for (int og = 0; og < 4; og++) deform_og(og, py, px, dil, lane8, prow, qb, wsh, a0, a1, a2, 0);
#pragma unroll 1
    for (int og = 4; og < 8; og++) deform_og(og, py, px, dil, lane8, prow, qb, wsh, a3, a4, a5, 3);
    float acc[6] = {a0, a1, a2, a3, a4, a5};
#pragma unroll
    for (int r = 0; r < 6; r++) {
        acc[r] += __shfl_xor_sync(0xffffffffu, acc[r], 1);
        acc[r] += __shfl_xor_sync(0xffffffffu, acc[r], 2);
        acc[r] += __shfl_xor_sync(0xffffffffu, acc[r], 4);
    }
    if (lane8 == 0) {
        size_t obase = ((size_t)b * 24 + 6 + dz * 6) * HWN + p;
#pragma unroll
        for (int r = 0; r < 6; r++) g_sim[obase + (size_t)r * HWN] = acc[r];
    }
}

__global__ void outconv_kernel(const float* __restrict__ ow, const float* __restrict__ ob,
                               float* __restrict__ out) {
    __shared__ float ws[256 * 25];
    __shared__ float st[24 * 65];
    int b = blockIdx.y;
    int m0 = blockIdx.x * 64;
    int tid = threadIdx.x;
    for (int i = tid; i < 6144; i += 256) {
        int oc = i / 24, k = i - oc * 24;
        ws[oc * 25 + k] = ow[i];
    }
    for (int i = tid; i < 24 * 64; i += 256) {
        int ch = i >> 6, j = i & 63;
        st[ch * 65 + j] = g_sim[((size_t)b * 24 + ch) * HWN + m0 + j];
    }
    __syncthreads();
    int j = tid & 63;
    int ocb = (tid >> 6) * 64;
    for (int oc = ocb; oc < ocb + 64; oc++) {
        float a = ob[oc];
#pragma unroll
        for (int k = 0; k < 24; k++) a += ws[oc * 25 + k] * st[k * 65 + j];
        out[((size_t)b * 256 + oc) * HWN + m0 + j] = a;
    }
}

extern "C" void kernel_launch(void* const* d_in, const int* in_sizes, int n_in,
                              void* d_out, int out_size) {
    const float* qf = (const float*)d_in[0];
    const float* sf = (const float*)d_in[1];
    const float* in_w = (const float*)d_in[2];
    const float* in_b = (const float*)d_in[3];
    const float* ln_g = (const float*)d_in[4];
    const float* ln_b = (const float*)d_in[5];
    const float* out_w = (const float*)d_in[6];
    const float* out_b = (const float*)d_in[7];
    const float* offw1 = (const float*)d_in[8];
    const float* offb1 = (const float*)d_in[9];
    const float* mskw1 = (const float*)d_in[10];
    const float* mskb1 = (const float*)d_in[11];
    const float* offw2 = (const float*)d_in[12];
    const float* offb2 = (const float*)d_in[13];
    const float* mskw2 = (const float*)d_in[14];
    const float* mskb2 = (const float*)d_in[15];
    const float* offw4 = (const float*)d_in[16];
    const float* offb4 = (const float*)d_in[17];
    const float* mskw4 = (const float*)d_in[18];
    const float* mskb4 = (const float*)d_in[19];
    float* out = (float*)d_out;

    cudaFuncSetAttribute(gemm_mma, cudaFuncAttributeMaxDynamicSharedMemorySize, SMEM_DYN);

    pack_wa<<<256, 256>>>(in_w);
    pack_bias<<<3, 256>>>(offb1, mskb1, offb2, mskb2, offb4, mskb4);
    pack_bin<<<CH_IN, 256>>>(in_w);
    pack_bbig<<<dim3(NT_BIG, CH_BIG), 256>>>(offw1, mskw1, offw2, mskw2, offw4, mskw4);
    prep_ain<<<dim3(MT_IN, CH_IN), 256>>>(qf);
    gemm_mma<<<MT_IN, 256, SMEM_DYN>>>(0, in_b);
    support_kernel<<<6, 256>>>(sf, in_b, ln_g, ln_b);
    ln_row<<<2304, 256>>>(ln_g, ln_b);
    gemm_mma<<<MT_BIG * NT_BIG, 256, SMEM_DYN>>>(1, nullptr);
    softmax_kernel<<<dim3(36, 3, 2), 256>>>();
    sim0_kernel<<<dim3(288, 2), 256>>>();
    deform_kernel<<<dim3(12, 24, 6), 256>>>();
    outconv_kernel<<<dim3(144, 2), 256>>>(out_w, out_b, out);
}

// round 6
// speedup vs baseline: 4.8171x; 1.5849x over previous
#include <cuda_runtime.h>
#include <cuda_fp16.h>
#include <stdint.h>

#define HWN 9216
#define CN 256
#define BB 2
#define NOUT 648
#define CH_BIG 36
#define CH_IN 4
#define NT_BIG 3
#define MT_IN 144
#define BTILES 75
#define MT_BIG (BB * BTILES)
#define PADW 98
#define PROWS 9856
#define QROWS 19712
#define RS_BIG 768

__device__ __align__(128) __half g_qpad[(size_t)4 * QROWS * 64];
__device__ __align__(128) __half g_Ain[(size_t)MT_IN * CH_IN * 8192];
__device__ __align__(128) __half g_Bbig[(size_t)NT_BIG * CH_BIG * 16384];
__device__ __align__(128) __half g_Bin[(size_t)CH_IN * 16384];
__device__ float g_qpre[BB * HWN * CN];
__device__ float g_qhwc[BB * HWN * CN];
__device__ float g_conv2[(size_t)BB * HWN * RS_BIG];
__device__ float g_WA[CN * CN];
__device__ float g_sW[BB * 3 * CN * 9];
__device__ float g_pool[BB * 6 * 128];
__device__ float g_sim[BB * 24 * HWN];
__device__ __align__(16) float g_bpack[768];

__device__ __forceinline__ uint32_t smem_u32(const void* p) {
    uint32_t a;
    asm("{ .reg .u64 t; cvta.to.shared.u64 t, %1; cvt.u32.u64 %0, t; }" : "=r"(a) : "l"(p));
    return a;
}
#define MBINIT(a, c) asm volatile("mbarrier.init.shared.b64 [%0], %1;" ::"r"(a), "r"(c) : "memory")
#define MBEXPECT(a, b) \
    asm volatile("mbarrier.arrive.expect_tx.shared.b64 _, [%0], %1;" ::"r"(a), "r"(b) : "memory")
__device__ __forceinline__ void mbar_wait(uint32_t mbar, uint32_t parity) {
    asm volatile(
        "{\n\t.reg .pred P;\n\t"
        "LAB_%=:\n\t"
        "mbarrier.try_wait.parity.acquire.cta.shared::cta.b64 P, [%0], %1, 0x989680;\n\t"
        "@!P bra LAB_%=;\n\t}" ::"r"(mbar), "r"(parity) : "memory");
}
__device__ __forceinline__ void bulk_g2s(uint32_t dst, const void* src, uint32_t bytes, uint32_t mbar) {
    asm volatile(
        "cp.async.bulk.shared::cluster.global.mbarrier::complete_tx::bytes [%0], [%1], %2, [%3];"
        ::"r"(dst), "l"(src), "r"(bytes), "r"(mbar) : "memory");
}
__device__ __forceinline__ void ldsm4(uint32_t* r, uint32_t addr) {
    asm volatile("ldmatrix.sync.aligned.m8n8.x4.shared.b16 {%0,%1,%2,%3}, [%4];"
                 : "=r"(r[0]), "=r"(r[1]), "=r"(r[2]), "=r"(r[3]) : "r"(addr));
}
__device__ __forceinline__ void mma_f16(float* c, const uint32_t* a, const uint32_t* b) {
    asm volatile(
        "mma.sync.aligned.m16n8k16.row.col.f32.f16.f16.f32 "
        "{%0,%1,%2,%3}, {%4,%5,%6,%7}, {%8,%9}, {%0,%1,%2,%3};"
        : "+f"(c[0]), "+f"(c[1]), "+f"(c[2]), "+f"(c[3])
        : "r"(a[0]), "r"(a[1]), "r"(a[2]), "r"(a[3]), "r"(b[0]), "r"(b[1]));
}
__device__ __forceinline__ void cvt8(const float* v, __half* hv) {
#pragma unroll
    for (int j = 0; j < 8; j++) hv[j] = __float2half_rn(v[j]);
}

__global__ void pack_wa(const float* __restrict__ inw) {
    int idx = blockIdx.x * 256 + threadIdx.x;
    int k = idx >> 8, n = idx & 255;
    g_WA[k * CN + n] = inw[n * CN + k];
}

__global__ void pack_bias(const float* __restrict__ ob1, const float* __restrict__ mb1,
                          const float* __restrict__ ob2, const float* __restrict__ mb2,
                          const float* __restrict__ ob4, const float* __restrict__ mb4) {
    int idx = blockIdx.x * 256 + threadIdx.x;
    if (idx >= 768) return;
    float v = 0.f;
    if (idx < NOUT) {
        int d = idx / 216, r = idx - d * 216;
        const float* bb = (r < 144) ? (d == 0 ? ob1 : d == 1 ? ob2 : ob4)
                                    : (d == 0 ? mb1 : d == 1 ? mb2 : mb4);
        v = bb[(r < 144) ? r : r - 144];
    }
    g_bpack[idx] = v;
}

__global__ void pack_bin(const float* __restrict__ inw) {
    int chunk = blockIdx.x;
    int c0 = chunk * 64;
    char* dst = (char*)(g_Bin + (size_t)chunk * 16384);
    int tid = threadIdx.x;
#pragma unroll
    for (int i = 0; i < 8; i++) {
        int unit = i * 256 + tid;
        int r = unit >> 3, u = unit & 7;
        float v[8];
#pragma unroll
        for (int j = 0; j < 8; j++) v[j] = inw[(size_t)r * 256 + c0 + u * 8 + j];
        __align__(16) __half hv[8];
        cvt8(v, hv);
        uint32_t off = r * 128 + u * 16;
        uint32_t sw = off ^ ((off >> 3) & 0x70);
        *(uint4*)(dst + sw) = *(uint4*)hv;
    }
}

__global__ void pack_bbig(const float* __restrict__ ow1, const float* __restrict__ mw1,
                          const float* __restrict__ ow2, const float* __restrict__ mw2,
                          const float* __restrict__ ow4, const float* __restrict__ mw4) {
    int nt = blockIdx.x, chunk = blockIdx.y;
    int tap = chunk >> 2;
    int c0 = (chunk & 3) * 64;
    char* dst = (char*)(g_Bbig + (size_t)(nt * CH_BIG + chunk) * 16384);
    int tid = threadIdx.x;
#pragma unroll
    for (int i = 0; i < 8; i++) {
        int unit = i * 256 + tid;
        int r = unit >> 3, u = unit & 7;
        int n = nt * 256 + r;
        float v[8];
#pragma unroll
        for (int j = 0; j < 8; j++) v[j] = 0.f;
        if (n < NOUT) {
            int d = n / 216, rr = n - d * 216;
            const float* w = (rr < 144) ? (d == 0 ? ow1 : d == 1 ? ow2 : ow4)
                                        : (d == 0 ? mw1 : d == 1 ? mw2 : mw4);
            int oc = (rr < 144) ? rr : rr - 144;
#pragma unroll
            for (int j = 0; j < 8; j++)
                v[j] = w[(size_t)oc * 2304 + (size_t)(c0 + u * 8 + j) * 9 + tap];
        }
        __align__(16) __half hv[8];
        cvt8(v, hv);
        uint32_t off = r * 128 + u * 16;
        uint32_t sw = off ^ ((off >> 3) & 0x70);
        *(uint4*)(dst + sw) = *(uint4*)hv;
    }
}

__global__ void prep_ain(const float* __restrict__ qf) {
    int mt = blockIdx.x, chunk = blockIdx.y;
    int c0 = chunk * 64;
    char* dst = (char*)(g_Ain + (size_t)(mt * CH_IN + chunk) * 8192);
    int tid = threadIdx.x;
#pragma unroll
    for (int i = 0; i < 4; i++) {
        int unit = i * 256 + tid;
        int r = unit & 127, u = unit >> 7;
        int m = mt * 128 + r;
        int b = m / HWN, p = m - b * HWN;
        float v[8];
#pragma unroll
        for (int j = 0; j < 8; j++) v[j] = qf[((size_t)b * CN + c0 + u * 8 + j) * HWN + p];
        __align__(16) __half hv[8];
        cvt8(v, hv);
        uint32_t off = r * 128 + u * 16;
        uint32_t sw = off ^ ((off >> 3) & 0x70);
        *(uint4*)(dst + sw) = *(uint4*)hv;
    }
}

#define STGB 49152
#define SMEM_DYN (1024 + 3 * STGB)

__global__ __launch_bounds__(256, 1) void gemm_mma(int which, const float* __restrict__ bias_in) {
    extern __shared__ char smraw[];
    char* basep = (char*)(((uintptr_t)smraw + 1023) & ~(uintptr_t)1023);
    uint32_t sb = smem_u32(basep);
    const int chunks = which ? CH_BIG : CH_IN;
    const int ntiles = which ? NT_BIG : 1;
    const float* bias = which ? g_bpack : bias_in;
    int bx = blockIdx.x;
    int mt = bx / ntiles, nt = bx - (bx / ntiles) * ntiles;
    int b = 0, mt_local = mt;
    size_t arowbase = 0;
    if (which) {
        b = mt / BTILES;
        mt_local = mt - b * BTILES;
        arowbase = (size_t)b * PROWS + 128 + (size_t)mt_local * 128;
    }
    int tid = threadIdx.x, wid = tid >> 5, lane = tid & 31;
    int wm = (wid & 3) * 32, wn = (wid >> 2) * 128;
    uint32_t FULLB = sb, STG = sb + 1024;

    if (tid == 0)
        for (int s = 0; s < 3; s++) MBINIT(FULLB + s * 8, 1);
    __syncthreads();

    auto issue = [&](int ch, int st) {
        uint32_t S = STG + st * STGB;
        MBEXPECT(FULLB + st * 8, 49152u);
        if (which) {
            int tap = ch >> 2, cq = ch & 3;
            int shift = (tap / 3 - 1) * PADW + (tap % 3 - 1);
            size_t row0 = arowbase + shift;
            bulk_g2s(S, g_qpad + ((size_t)cq * QROWS + row0) * 64, 16384u, FULLB + st * 8);
            bulk_g2s(S + 16384, g_Bbig + (size_t)(nt * CH_BIG + ch) * 16384, 32768u, FULLB + st * 8);
        } else {
            bulk_g2s(S, g_Ain + (size_t)(mt * CH_IN + ch) * 8192, 16384u, FULLB + st * 8);
            bulk_g2s(S + 16384, g_Bin + (size_t)ch * 16384, 32768u, FULLB + st * 8);
        }
    };
    if (tid == 0) {
        int pre = chunks < 3 ? chunks : 3;
        for (int s = 0; s < pre; s++) issue(s, s);
    }

    float acc[2][16][4];
#pragma unroll
    for (int a = 0; a < 2; a++)
#pragma unroll
        for (int n = 0; n < 16; n++)
#pragma unroll
            for (int c = 0; c < 4; c++) acc[a][n][c] = 0.f;

    int x7 = lane & 7;
    int kuA = lane >> 4;
    int kuB = (lane >> 3) & 1;
    uint32_t offA[2], offB[8];
#pragma unroll
    for (int mt2 = 0; mt2 < 2; mt2++)
        offA[mt2] = (uint32_t)(wm + mt2 * 16 + ((lane >> 3) & 1) * 8 + x7) * 128u;
#pragma unroll
    for (int ng = 0; ng < 8; ng++)
        offB[ng] = (uint32_t)(wn + ng * 16 + ((lane >> 4) << 3) + x7) * 128u;

    for (int ch = 0; ch < chunks; ch++) {
        int st = ch % 3;
        mbar_wait(FULLB + st * 8, (uint32_t)((ch / 3) & 1));
        uint32_t aB = STG + st * STGB;
        uint32_t bB = aB + 16384;
        int xA = x7;
        if (which) {
            int tap = ch >> 2;
            int shift = (tap / 3 - 1) * PADW + (tap % 3 - 1);
            xA = (x7 + shift) & 7;
        }
#pragma unroll
        for (int ks = 0; ks < 4; ks++) {
            uint32_t cA = (uint32_t)(((ks * 2 + kuA) ^ xA) << 4);
            uint32_t cB = (uint32_t)(((ks * 2 + kuB) ^ x7) << 4);
            uint32_t Ah[2][4];
#pragma unroll
            for (int mt2 = 0; mt2 < 2; mt2++) ldsm4(Ah[mt2], aB + offA[mt2] + cA);
#pragma unroll
            for (int ng = 0; ng < 8; ng++) {
                uint32_t Bh[4];
                ldsm4(Bh, bB + offB[ng] + cB);
#pragma unroll
                for (int h = 0; h < 2; h++) {
                    int n8 = ng * 2 + h;
                    mma_f16(acc[0][n8], Ah[0], &Bh[h * 2]);
                    mma_f16(acc[1][n8], Ah[1], &Bh[h * 2]);
                }
            }
        }
        __syncthreads();
        if (tid == 0 && ch + 3 < chunks) issue(ch + 3, st);
    }

    if (which) {
#pragma unroll
        for (int mt2 = 0; mt2 < 2; mt2++) {
#pragma unroll
            for (int half = 0; half < 2; half++) {
                int r = wm + mt2 * 16 + (lane >> 2) + half * 8;
                int pp = mt_local * 128 + r;
                int yq = pp / PADW, xq = pp - yq * PADW;
                bool ok = (yq >= 1) && (yq <= 96) && (xq >= 1) && (xq <= 96);
                if (!ok) continue;
                float* drow = g_conv2 + ((size_t)(b * HWN + (yq - 1) * 96 + xq - 1)) * RS_BIG;
#pragma unroll
                for (int n8 = 0; n8 < 16; n8++) {
                    int col = nt * 256 + wn + n8 * 8 + (lane & 3) * 2;
                    float2 v = make_float2(acc[mt2][n8][half * 2 + 0] + bias[col],
                                           acc[mt2][n8][half * 2 + 1] + bias[col + 1]);
                    *(float2*)&drow[col] = v;
                }
            }
        }
    } else {
#pragma unroll
        for (int mt2 = 0; mt2 < 2; mt2++) {
#pragma unroll
            for (int half = 0; half < 2; half++) {
                int r = wm + mt2 * 16 + (lane >> 2) + half * 8;
                float* drow = g_qpre + (size_t)(mt * 128 + r) * 256;
#pragma unroll
                for (int n8 = 0; n8 < 16; n8++) {
                    int col = wn + n8 * 8 + (lane & 3) * 2;
                    float2 v = make_float2(acc[mt2][n8][half * 2 + 0] + bias[col],
                                           acc[mt2][n8][half * 2 + 1] + bias[col + 1]);
                    *(float2*)&drow[col] = v;
                }
            }
        }
    }
}

__global__ void ln_row(const float* __restrict__ gam, const float* __restrict__ bet) {
    int m = blockIdx.x * 8 + (threadIdx.x >> 5);
    int lane = threadIdx.x & 31;
    const float* src = g_qpre + (size_t)m * 256 + lane * 8;
    float4 a = *(const float4*)src;
    float4 b4 = *(const float4*)(src + 4);
    float v[8] = {a.x, a.y, a.z, a.w, b4.x, b4.y, b4.z, b4.w};
    float s1 = 0.f, s2 = 0.f;
#pragma unroll
    for (int j = 0; j < 8; j++) { s1 += v[j]; s2 += v[j] * v[j]; }
#pragma unroll
    for (int o = 16; o > 0; o >>= 1) {
        s1 += __shfl_xor_sync(0xffffffffu, s1, o);
        s2 += __shfl_xor_sync(0xffffffffu, s2, o);
    }
    float mu = s1 * (1.f / 256.f);
    float rv = rsqrtf(s2 * (1.f / 256.f) - mu * mu + 1e-5f);
#pragma unroll
    for (int j = 0; j < 8; j++) {
        int c = lane * 8 + j;
        v[j] = (v[j] - mu) * rv * __ldg(&gam[c]) + __ldg(&bet[c]);
    }
    float* dst = g_qhwc + (size_t)m * 256 + lane * 8;
    *(float4*)dst = make_float4(v[0], v[1], v[2], v[3]);
    *(float4*)(dst + 4) = make_float4(v[4], v[5], v[6], v[7]);
    int b = m / HWN, p = m - b * HWN;
    int y = p / 96, x = p - y * 96;
    size_t r_abs = (size_t)b * PROWS + 128 + (size_t)(y + 1) * PADW + (x + 1);
    int cq = lane >> 3, u = lane & 7;
    uint32_t sw = (uint32_t)(u * 16) ^ (((uint32_t)r_abs & 7) << 4);
    __align__(16) __half hv[8];
    cvt8(v, hv);
    char* hb = (char*)(g_qpad + ((size_t)cq * QROWS + r_abs) * 64);
    *(uint4*)(hb + sw) = *(uint4*)hv;
}

__global__ void support_kernel(const float* __restrict__ sup, const float* __restrict__ inb,
                               const float* __restrict__ gam, const float* __restrict__ bet) {
    __shared__ float xs[2304];
    __shared__ float Wt[32 * 256];
    __shared__ float stats[18];
    int bid = blockIdx.x;
    int b = bid / 3, ex = bid - b * 3;
    int tid = threadIdx.x;
    const float* sp = sup + (size_t)(b * 3 + ex) * 2304;
    for (int i = tid; i < 2304; i += 256) xs[i] = sp[i];
    float acc[9];
    float bia = inb[tid];
#pragma unroll
    for (int pos = 0; pos < 9; pos++) acc[pos] = bia;
    for (int k0 = 0; k0 < 256; k0 += 32) {
        __syncthreads();
        const float4* src = (const float4*)(g_WA + k0 * 256);
        float4* dW = (float4*)Wt;
        for (int i = tid; i < 2048; i += 256) dW[i] = src[i];
        __syncthreads();
#pragma unroll
        for (int kk = 0; kk < 32; kk++) {
            float w = Wt[kk * 256 + tid];
#pragma unroll
            for (int pos = 0; pos < 9; pos++) acc[pos] += w * xs[(k0 + kk) * 9 + pos];
        }
    }
    __syncthreads();
#pragma unroll
    for (int pos = 0; pos < 9; pos++) xs[tid * 9 + pos] = acc[pos];
    __syncthreads();
    if (tid < 9) {
        float s1 = 0.f, s2 = 0.f;
        for (int c = 0; c < 256; c++) { float v = xs[c * 9 + tid]; s1 += v; s2 += v * v; }
        float mu = s1 * (1.f / 256.f);
        stats[tid] = mu;
        stats[9 + tid] = rsqrtf(s2 * (1.f / 256.f) - mu * mu + 1e-5f);
    }
    __syncthreads();
    float mx = -1e30f;
    float g = gam[tid], be = bet[tid];
#pragma unroll
    for (int pos = 0; pos < 9; pos++) {
        float v = (acc[pos] - stats[pos]) * stats[9 + pos] * g + be;
        g_sW[((size_t)(b * 3 + ex) * 256 + tid) * 9 + pos] = v;
        mx = fmaxf(mx, v);
    }
    int r = ex * 2 + (tid >> 7);
    g_pool[(b * 6 + r) * 128 + (tid & 127)] = mx;
}

__global__ void softmax_kernel() {
    int p = blockIdx.x * 256 + threadIdx.x;
    int dz = blockIdx.y, b = blockIdx.z;
    float* base = g_conv2 + ((size_t)(b * HWN) + p) * RS_BIG + dz * 216 + 144;
    float4 e[18];
    float mx = -1e30f;
#pragma unroll
    for (int i = 0; i < 18; i++) {
        e[i] = *(float4*)&base[i * 4];
        mx = fmaxf(mx, fmaxf(fmaxf(e[i].x, e[i].y), fmaxf(e[i].z, e[i].w)));
    }
    float s = 0.f;
#pragma unroll
    for (int i = 0; i < 18; i++) {
        e[i].x = expf(e[i].x - mx); e[i].y = expf(e[i].y - mx);
        e[i].z = expf(e[i].z - mx); e[i].w = expf(e[i].w - mx);
        s += e[i].x + e[i].y + e[i].z + e[i].w;
    }
    float inv = 1.f / s;
#pragma unroll
    for (int i = 0; i < 18; i++) {
        e[i].x *= inv; e[i].y *= inv; e[i].z *= inv; e[i].w *= inv;
        *(float4*)&base[i * 4] = e[i];
    }
}

__global__ void sim0_kernel() {
    __shared__ __align__(16) float psh[6 * 128];
    int b = blockIdx.y;
    int tid = threadIdx.x;
    int lane8 = tid & 7, pl = tid >> 3;
    int pg = blockIdx.x * 32 + pl;
    for (int i = tid; i < 768; i += 256) psh[i] = g_pool[b * 768 + i];
    __syncthreads();
    const float* qrow = g_qhwc + ((size_t)b * HWN + pg) * CN;
    float acc[6];
#pragma unroll
    for (int r = 0; r < 6; r++) acc[r] = 0.f;
#pragma unroll
    for (int r = 0; r < 6; r++) {
        int g = (r >= 3) ? 1 : 0;
#pragma unroll
        for (int qq = 0; qq < 4; qq++) {
            int f = lane8 + qq * 8;
            float4 qv = *(const float4*)&qrow[g * 128 + f * 4];
            float4 pv = *(const float4*)&psh[r * 128 + f * 4];
            acc[r] += qv.x * pv.x + qv.y * pv.y + qv.z * pv.z + qv.w * pv.w;
        }
    }
#pragma unroll
    for (int r = 0; r < 6; r++) {
        acc[r] += __shfl_xor_sync(0xffffffffu, acc[r], 1);
        acc[r] += __shfl_xor_sync(0xffffffffu, acc[r], 2);
        acc[r] += __shfl_xor_sync(0xffffffffu, acc[r], 4);
    }
    if (lane8 == 0)
#pragma unroll
        for (int r = 0; r < 6; r++) g_sim[((size_t)b * 24 + r) * HWN + pg] = acc[r];
}

__device__ __forceinline__ void deform_og(
    int og, int py, int px, int dil, int lane8,
    const float* __restrict__ prow, const float* __restrict__ qb, const float* wsh,
    float& a0, float& a1, float& a2, int rbase) {
    int cb = og * 32 + lane8 * 4;
    int cgrp = (og & 3) * 32 + lane8 * 4;
#pragma unroll
    for (int tap = 0; tap < 9; tap++) {
        float dy = prow[og * 18 + tap * 2];
        float dx = prow[og * 18 + tap * 2 + 1];
        float m = prow[144 + og * 9 + tap];
        float fy = (float)(py + (tap / 3) * dil - dil) + dy;
        float fx = (float)(px + (tap % 3) * dil - dil) + dx;
        float y0f = floorf(fy), x0f = floorf(fx);
        float wy = fy - y0f, wx = fx - x0f;
        int y0 = (int)y0f, x0 = (int)x0f;
        float w00 = (1.f - wy) * (1.f - wx) * m, w01 = (1.f - wy) * wx * m;
        float w10 = wy * (1.f - wx) * m, w11 = wy * wx * m;
        bool y0v = (unsigned)y0 < 96u, y1v = (unsigned)(y0 + 1) < 96u;
        bool x0v = (unsigned)x0 < 96u, x1v = (unsigned)(x0 + 1) < 96u;
        float vx = 0.f, vy = 0.f, vz = 0.f, vw = 0.f;
        if (y0v && x0v) {
            float4 t = *(const float4*)&qb[(size_t)(y0 * 96 + x0) * 256 + cb];
            vx += w00 * t.x; vy += w00 * t.y; vz += w00 * t.z; vw += w00 * t.w;
        }
        if (y0v && x1v) {
            float4 t = *(const float4*)&qb[(size_t)(y0 * 96 + x0 + 1) * 256 + cb];
            vx += w01 * t.x; vy += w01 * t.y; vz += w01 * t.z; vw += w01 * t.w;
        }
        if (y1v && x0v) {
            float4 t = *(const float4*)&qb[(size_t)((y0 + 1) * 96 + x0) * 256 + cb];
            vx += w10 * t.x; vy += w10 * t.y; vz += w10 * t.z; vw += w10 * t.w;
        }
        if (y1v && x1v) {
            float4 t = *(const float4*)&qb[(size_t)((y0 + 1) * 96 + x0 + 1) * 256 + cb];
            vx += w11 * t.x; vy += w11 * t.y; vz += w11 * t.z; vw += w11 * t.w;
        }
        float4 w0 = *(const float4*)&wsh[((rbase + 0) * 9 + tap) * 128 + cgrp];
        a0 += vx * w0.x + vy * w0.y + vz * w0.z + vw * w0.w;
        float4 w1 = *(const float4*)&wsh[((rbase + 1) * 9 + tap) * 128 + cgrp];
        a1 += vx * w1.x + vy * w1.y + vz * w1.z + vw * w1.w;
        float4 w2 = *(const float4*)&wsh[((rbase + 2) * 9 + tap) * 128 + cgrp];
        a2 += vx * w2.x + vy * w2.y + vz * w2.z + vw * w2.w;
    }
}

__global__ void deform_kernel() {
    __shared__ __align__(16) float wsh[6 * 9 * 128];
    int z = blockIdx.z;
    int b = z / 3, dz = z - b * 3;
    int dil = 1 << dz;
    int tid = threadIdx.x;
    int lane8 = tid & 7, pl = tid >> 3;
    int px = blockIdx.x * 8 + (pl & 7);
    int py = blockIdx.y * 4 + (pl >> 3);
    int p = py * 96 + px;
    for (int i = tid; i < 6912; i += 256) {
        int r = i / 1152;
        int rem = i - r * 1152;
        int tap = rem >> 7;
        int cg = rem & 127;
        int ex = r >> 1, half = r & 1;
        wsh[i] = g_sW[((size_t)(b * 3 + ex) * 256 + half * 128 + cg) * 9 + tap];
    }
    __syncthreads();
    const float* prow = g_conv2 + ((size_t)(b * HWN) + p) * RS_BIG + dz * 216;
    const float* qb = g_qhwc + (size_t)b * HWN * CN;
    float a0 = 0.f, a1 = 0.f, a2 = 0.f, a3 = 0.f, a4 = 0.f, a5 = 0.f;
#pragma unroll 1
    for (int og = 0; og < 4; og++) deform_og(og, py, px, dil, lane8, prow, qb, wsh, a0, a1, a2, 0);
#pragma unroll 1
    for (int og = 4; og < 8; og++) deform_og(og, py, px, dil, lane8, prow, qb, wsh, a3, a4, a5, 3);
    float acc[6] = {a0, a1, a2, a3, a4, a5};
#pragma unroll
    for (int r = 0; r < 6; r++) {
        acc[r] += __shfl_xor_sync(0xffffffffu, acc[r], 1);
        acc[r] += __shfl_xor_sync(0xffffffffu, acc[r], 2);
        acc[r] += __shfl_xor_sync(0xffffffffu, acc[r], 4);
    }
    if (lane8 == 0) {
        size_t obase = ((size_t)b * 24 + 6 + dz * 6) * HWN + p;
#pragma unroll
        for (int r = 0; r < 6; r++) g_sim[obase + (size_t)r * HWN] = acc[r];
    }
}

__global__ void outconv_kernel(const float* __restrict__ ow, const float* __restrict__ ob,
                               float* __restrict__ out) {
    __shared__ float ws[256 * 25];
    __shared__ float st[24 * 65];
    int b = blockIdx.y;
    int m0 = blockIdx.x * 64;
    int tid = threadIdx.x;
    for (int i = tid; i < 6144; i += 256) {
        int oc = i / 24, k = i - oc * 24;
        ws[oc * 25 + k] = ow[i];
    }
    for (int i = tid; i < 24 * 64; i += 256) {
        int ch = i >> 6, j = i & 63;
        st[ch * 65 + j] = g_sim[((size_t)b * 24 + ch) * HWN + m0 + j];
    }
    __syncthreads();
    int j = tid & 63;
    int ocb = (tid >> 6) * 64;
    for (int oc = ocb; oc < ocb + 64; oc++) {
        float a = ob[oc];
#pragma unroll
        for (int k = 0; k < 24; k++) a += ws[oc * 25 + k] * st[k * 65 + j];
        out[((size_t)b * 256 + oc) * HWN + m0 + j] = a;
    }
}

extern "C" void kernel_launch(void* const* d_in, const int* in_sizes, int n_in,
                              void* d_out, int out_size) {
    const float* qf = (const float*)d_in[0];
    const float* sf = (const float*)d_in[1];
    const float* in_w = (const float*)d_in[2];
    const float* in_b = (const float*)d_in[3];
    const float* ln_g = (const float*)d_in[4];
    const float* ln_b = (const float*)d_in[5];
    const float* out_w = (const float*)d_in[6];
    const float* out_b = (const float*)d_in[7];
    const float* offw1 = (const float*)d_in[8];
    const float* offb1 = (const float*)d_in[9];
    const float* mskw1 = (const float*)d_in[10];
    const float* mskb1 = (const float*)d_in[11];
    const float* offw2 = (const float*)d_in[12];
    const float* offb2 = (const float*)d_in[13];
    const float* mskw2 = (const float*)d_in[14];
    const float* mskb2 = (const float*)d_in[15];
    const float* offw4 = (const float*)d_in[16];
    const float* offb4 = (const float*)d_in[17];
    const float* mskw4 = (const float*)d_in[18];
    const float* mskb4 = (const float*)d_in[19];
    float* out = (float*)d_out;

    cudaFuncSetAttribute(gemm_mma, cudaFuncAttributeMaxDynamicSharedMemorySize, SMEM_DYN);

    pack_wa<<<256, 256>>>(in_w);
    pack_bias<<<3, 256>>>(offb1, mskb1, offb2, mskb2, offb4, mskb4);
    pack_bin<<<CH_IN, 256>>>(in_w);
    pack_bbig<<<dim3(NT_BIG, CH_BIG), 256>>>(offw1, mskw1, offw2, mskw2, offw4, mskw4);
    prep_ain<<<dim3(MT_IN, CH_IN), 256>>>(qf);
    gemm_mma<<<MT_IN, 256, SMEM_DYN>>>(0, in_b);
    support_kernel<<<6, 256>>>(sf, in_b, ln_g, ln_b);
    ln_row<<<2304, 256>>>(ln_g, ln_b);
    gemm_mma<<<MT_BIG * NT_BIG, 256, SMEM_DYN>>>(1, nullptr);
    softmax_kernel<<<dim3(36, 3, 2), 256>>>();
    sim0_kernel<<<dim3(288, 2), 256>>>();
    deform_kernel<<<dim3(12, 24, 6), 256>>>();
    outconv_kernel<<<dim3(144, 2), 256>>>(out_w, out_b, out);
}

// round 7
// speedup vs baseline: 5.0963x; 1.0579x over previous
#include <cuda_runtime.h>
#include <cuda_fp16.h>
#include <stdint.h>

#define HWN 9216
#define CN 256
#define BB 2
#define NOUT 648
#define CH_BIG 36
#define CH_IN 4
#define NT_BIG 3
#define MT_IN 144
#define BT64 150
#define PADW 98
#define PROWS 9856
#define QROWS 19712
#define RS_BIG 768

__device__ __align__(128) __half g_qpad[(size_t)4 * QROWS * 64];
__device__ __align__(128) __half g_qh16[(size_t)BB * HWN * 256];
__device__ __align__(128) __half g_Ain[(size_t)MT_IN * CH_IN * 8192];
__device__ __align__(128) __half g_Bbig[(size_t)NT_BIG * CH_BIG * 16384];
__device__ __align__(128) __half g_Bin[(size_t)CH_IN * 16384];
__device__ float g_qpre[BB * HWN * CN];
__device__ float g_conv2[(size_t)BB * HWN * RS_BIG];
__device__ float g_WA[CN * CN];
__device__ float g_sW[BB * 3 * CN * 9];
__device__ float g_pool[BB * 6 * 128];
__device__ float g_sim[BB * 24 * HWN];
__device__ __align__(16) float g_bpack[768];

__device__ __forceinline__ uint32_t smem_u32(const void* p) {
    uint32_t a;
    asm("{ .reg .u64 t; cvta.to.shared.u64 t, %1; cvt.u32.u64 %0, t; }" : "=r"(a) : "l"(p));
    return a;
}
#define MBINIT(a, c) asm volatile("mbarrier.init.shared.b64 [%0], %1;" ::"r"(a), "r"(c) : "memory")
#define MBEXPECT(a, b) \
    asm volatile("mbarrier.arrive.expect_tx.shared.b64 _, [%0], %1;" ::"r"(a), "r"(b) : "memory")
__device__ __forceinline__ void mbar_wait(uint32_t mbar, uint32_t parity) {
    asm volatile(
        "{\n\t.reg .pred P;\n\t"
        "LAB_%=:\n\t"
        "mbarrier.try_wait.parity.acquire.cta.shared::cta.b64 P, [%0], %1, 0x989680;\n\t"
        "@!P bra LAB_%=;\n\t}" ::"r"(mbar), "r"(parity) : "memory");
}
__device__ __forceinline__ void bulk_g2s(uint32_t dst, const void* src, uint32_t bytes, uint32_t mbar) {
    asm volatile(
        "cp.async.bulk.shared::cluster.global.mbarrier::complete_tx::bytes [%0], [%1], %2, [%3];"
        ::"r"(dst), "l"(src), "r"(bytes), "r"(mbar) : "memory");
}
__device__ __forceinline__ void ldsm4(uint32_t* r, uint32_t addr) {
    asm volatile("ldmatrix.sync.aligned.m8n8.x4.shared.b16 {%0,%1,%2,%3}, [%4];"
                 : "=r"(r[0]), "=r"(r[1]), "=r"(r[2]), "=r"(r[3]) : "r"(addr));
}
__device__ __forceinline__ void mma_f16(float* c, const uint32_t* a, const uint32_t* b) {
    asm volatile(
        "mma.sync.aligned.m16n8k16.row.col.f32.f16.f16.f32 "
        "{%0,%1,%2,%3}, {%4,%5,%6,%7}, {%8,%9}, {%0,%1,%2,%3};"
        : "+f"(c[0]), "+f"(c[1]), "+f"(c[2]), "+f"(c[3])
        : "r"(a[0]), "r"(a[1]), "r"(a[2]), "r"(a[3]), "r"(b[0]), "r"(b[1]));
}
__device__ __forceinline__ void cvt8(const float* v, __half* hv) {
#pragma unroll
    for (int j = 0; j < 8; j++) hv[j] = __float2half_rn(v[j]);
}

__global__ void pack_wa(const float* __restrict__ inw) {
    int idx = blockIdx.x * 256 + threadIdx.x;
    int k = idx >> 8, n = idx & 255;
    g_WA[k * CN + n] = inw[n * CN + k];
}

__global__ void pack_bias(const float* __restrict__ ob1, const float* __restrict__ mb1,
                          const float* __restrict__ ob2, const float* __restrict__ mb2,
                          const float* __restrict__ ob4, const float* __restrict__ mb4) {
    int idx = blockIdx.x * 256 + threadIdx.x;
    if (idx >= 768) return;
    float v = 0.f;
    if (idx < NOUT) {
        int d = idx / 216, r = idx - d * 216;
        const float* bb = (r < 144) ? (d == 0 ? ob1 : d == 1 ? ob2 : ob4)
                                    : (d == 0 ? mb1 : d == 1 ? mb2 : mb4);
        v = bb[(r < 144) ? r : r - 144];
    }
    g_bpack[idx] = v;
}

__global__ void pack_bin(const float* __restrict__ inw) {
    int chunk = blockIdx.x;
    int c0 = chunk * 64;
    char* dst = (char*)(g_Bin + (size_t)chunk * 16384);
    int tid = threadIdx.x;
#pragma unroll
    for (int i = 0; i < 8; i++) {
        int unit = i * 256 + tid;
        int r = unit >> 3, u = unit & 7;
        float v[8];
#pragma unroll
        for (int j = 0; j < 8; j++) v[j] = inw[(size_t)r * 256 + c0 + u * 8 + j];
        __align__(16) __half hv[8];
        cvt8(v, hv);
        uint32_t off = r * 128 + u * 16;
        uint32_t sw = off ^ ((off >> 3) & 0x70);
        *(uint4*)(dst + sw) = *(uint4*)hv;
    }
}

__global__ void pack_bbig(const float* __restrict__ ow1, const float* __restrict__ mw1,
                          const float* __restrict__ ow2, const float* __restrict__ mw2,
                          const float* __restrict__ ow4, const float* __restrict__ mw4) {
    int nt = blockIdx.x, chunk = blockIdx.y;
    int tap = chunk >> 2;
    int c0 = (chunk & 3) * 64;
    char* dst = (char*)(g_Bbig + (size_t)(nt * CH_BIG + chunk) * 16384);
    int tid = threadIdx.x;
#pragma unroll
    for (int i = 0; i < 8; i++) {
        int unit = i * 256 + tid;
        int r = unit >> 3, u = unit & 7;
        int n = nt * 256 + r;
        float v[8];
#pragma unroll
        for (int j = 0; j < 8; j++) v[j] = 0.f;
        if (n < NOUT) {
            int d = n / 216, rr = n - d * 216;
            const float* w = (rr < 144) ? (d == 0 ? ow1 : d == 1 ? ow2 : ow4)
                                        : (d == 0 ? mw1 : d == 1 ? mw2 : mw4);
            int oc = (rr < 144) ? rr : rr - 144;
#pragma unroll
            for (int j = 0; j < 8; j++)
                v[j] = w[(size_t)oc * 2304 + (size_t)(c0 + u * 8 + j) * 9 + tap];
        }
        __align__(16) __half hv[8];
        cvt8(v, hv);
        uint32_t off = r * 128 + u * 16;
        uint32_t sw = off ^ ((off >> 3) & 0x70);
        *(uint4*)(dst + sw) = *(uint4*)hv;
    }
}

__global__ void prep_ain(const float* __restrict__ qf) {
    int mt = blockIdx.x, chunk = blockIdx.y;
    int c0 = chunk * 64;
    char* dst = (char*)(g_Ain + (size_t)(mt * CH_IN + chunk) * 8192);
    int tid = threadIdx.x;
#pragma unroll
    for (int i = 0; i < 4; i++) {
        int unit = i * 256 + tid;
        int r = unit & 127, u = unit >> 7;
        int m = mt * 128 + r;
        int b = m / HWN, p = m - b * HWN;
        float v[8];
#pragma unroll
        for (int j = 0; j < 8; j++) v[j] = qf[((size_t)b * CN + c0 + u * 8 + j) * HWN + p];
        __align__(16) __half hv[8];
        cvt8(v, hv);
        uint32_t off = r * 128 + u * 16;
        uint32_t sw = off ^ ((off >> 3) & 0x70);
        *(uint4*)(dst + sw) = *(uint4*)hv;
    }
}

// ---- in-projection GEMM: M128 N256 K256, 3-stage ----
#define STGI 49152
#define SMEM_IN (1024 + 3 * STGI)
__global__ __launch_bounds__(256, 1) void gemm_in_k(const float* __restrict__ bias) {
    extern __shared__ char smraw[];
    char* basep = (char*)(((uintptr_t)smraw + 1023) & ~(uintptr_t)1023);
    uint32_t sb = smem_u32(basep);
    int mt = blockIdx.x;
    int tid = threadIdx.x, wid = tid >> 5, lane = tid & 31;
    int wm = (wid & 3) * 32, wn = (wid >> 2) * 128;
    uint32_t FULLB = sb, STG = sb + 1024;
    if (tid == 0)
        for (int s = 0; s < 3; s++) MBINIT(FULLB + s * 8, 1);
    __syncthreads();
    auto issue = [&](int ch, int st) {
        uint32_t S = STG + st * STGI;
        MBEXPECT(FULLB + st * 8, 49152u);
        bulk_g2s(S, g_Ain + (size_t)(mt * CH_IN + ch) * 8192, 16384u, FULLB + st * 8);
        bulk_g2s(S + 16384, g_Bin + (size_t)ch * 16384, 32768u, FULLB + st * 8);
    };
    if (tid == 0) { issue(0, 0); issue(1, 1); issue(2, 2); }
    float acc[2][16][4];
#pragma unroll
    for (int a = 0; a < 2; a++)
#pragma unroll
        for (int n = 0; n < 16; n++)
#pragma unroll
            for (int c = 0; c < 4; c++) acc[a][n][c] = 0.f;
    int x7 = lane & 7, kuA = lane >> 4, kuB = (lane >> 3) & 1;
    uint32_t offA[2], offB[8];
#pragma unroll
    for (int mt2 = 0; mt2 < 2; mt2++)
        offA[mt2] = (uint32_t)(wm + mt2 * 16 + ((lane >> 3) & 1) * 8 + x7) * 128u;
#pragma unroll
    for (int ng = 0; ng < 8; ng++)
        offB[ng] = (uint32_t)(wn + ng * 16 + ((lane >> 4) << 3) + x7) * 128u;
    for (int ch = 0; ch < CH_IN; ch++) {
        int st = ch % 3;
        mbar_wait(FULLB + st * 8, (uint32_t)((ch / 3) & 1));
        uint32_t aB = STG + st * STGI, bB = aB + 16384;
#pragma unroll
        for (int ks = 0; ks < 4; ks++) {
            uint32_t cA = (uint32_t)(((ks * 2 + kuA) ^ x7) << 4);
            uint32_t cB = (uint32_t)(((ks * 2 + kuB) ^ x7) << 4);
            uint32_t Ah[2][4];
#pragma unroll
            for (int mt2 = 0; mt2 < 2; mt2++) ldsm4(Ah[mt2], aB + offA[mt2] + cA);
#pragma unroll
            for (int ng = 0; ng < 8; ng++) {
                uint32_t Bh[4];
                ldsm4(Bh, bB + offB[ng] + cB);
#pragma unroll
                for (int h = 0; h < 2; h++) {
                    int n8 = ng * 2 + h;
                    mma_f16(acc[0][n8], Ah[0], &Bh[h * 2]);
                    mma_f16(acc[1][n8], Ah[1], &Bh[h * 2]);
                }
            }
        }
        __syncthreads();
        if (tid == 0 && ch + 3 < CH_IN) issue(ch + 3, st);
    }
#pragma unroll
    for (int mt2 = 0; mt2 < 2; mt2++)
#pragma unroll
        for (int half = 0; half < 2; half++) {
            int r = wm + mt2 * 16 + (lane >> 2) + half * 8;
            float* drow = g_qpre + (size_t)(mt * 128 + r) * 256;
#pragma unroll
            for (int n8 = 0; n8 < 16; n8++) {
                int col = wn + n8 * 8 + (lane & 3) * 2;
                float2 v = make_float2(acc[mt2][n8][half * 2 + 0] + bias[col],
                                       acc[mt2][n8][half * 2 + 1] + bias[col + 1]);
                *(float2*)&drow[col] = v;
            }
        }
}

// ---- big conv GEMM: M64 N256 K2304, 2-stage, 2 CTAs/SM ----
#define STGB 40960
#define SMEM_BIG (1024 + 2 * STGB)
__global__ __launch_bounds__(256, 2) void gemm_big_k() {
    extern __shared__ char smraw[];
    char* basep = (char*)(((uintptr_t)smraw + 1023) & ~(uintptr_t)1023);
    uint32_t sb = smem_u32(basep);
    int bx = blockIdx.x;
    int mt = bx / NT_BIG, nt = bx - (bx / NT_BIG) * NT_BIG;
    int b = mt / BT64, mt_local = mt - b * BT64;
    size_t arowbase = (size_t)b * PROWS + 128 + (size_t)mt_local * 64;
    int tid = threadIdx.x, wid = tid >> 5, lane = tid & 31;
    int wm = (wid & 1) * 32, wn = (wid >> 1) * 64;
    uint32_t FULLB = sb, STG = sb + 1024;
    if (tid == 0)
        for (int s = 0; s < 2; s++) MBINIT(FULLB + s * 8, 1);
    __syncthreads();
    auto issue = [&](int ch, int st) {
        uint32_t S = STG + st * STGB;
        MBEXPECT(FULLB + st * 8, 40960u);
        int tap = ch >> 2, cq = ch & 3;
        int shift = (tap / 3 - 1) * PADW + (tap % 3 - 1);
        size_t row0 = arowbase + shift;
        bulk_g2s(S, g_qpad + ((size_t)cq * QROWS + row0) * 64, 8192u, FULLB + st * 8);
        bulk_g2s(S + 8192, g_Bbig + (size_t)(nt * CH_BIG + ch) * 16384, 32768u, FULLB + st * 8);
    };
    if (tid == 0) { issue(0, 0); issue(1, 1); }
    float acc[2][8][4];
#pragma unroll
    for (int a = 0; a < 2; a++)
#pragma unroll
        for (int n = 0; n < 8; n++)
#pragma unroll
            for (int c = 0; c < 4; c++) acc[a][n][c] = 0.f;
    int x7 = lane & 7, kuA = lane >> 4, kuB = (lane >> 3) & 1;
    uint32_t offA[2], offB[4];
#pragma unroll
    for (int mt2 = 0; mt2 < 2; mt2++)
        offA[mt2] = (uint32_t)(wm + mt2 * 16 + ((lane >> 3) & 1) * 8 + x7) * 128u;
#pragma unroll
    for (int ng = 0; ng < 4; ng++)
        offB[ng] = (uint32_t)(wn + ng * 16 + ((lane >> 4) << 3) + x7) * 128u;
    for (int ch = 0; ch < CH_BIG; ch++) {
        int st = ch & 1;
        mbar_wait(FULLB + st * 8, (uint32_t)((ch >> 1) & 1));
        uint32_t aB = STG + st * STGB, bB = aB + 8192;
        int tap = ch >> 2;
        int shift = (tap / 3 - 1) * PADW + (tap % 3 - 1);
        int xA = (x7 + shift) & 7;
#pragma unroll
        for (int ks = 0; ks < 4; ks++) {
            uint32_t cA = (uint32_t)(((ks * 2 + kuA) ^ xA) << 4);
            uint32_t cB = (uint32_t)(((ks * 2 + kuB) ^ x7) << 4);
            uint32_t Ah[2][4];
#pragma unroll
            for (int mt2 = 0; mt2 < 2; mt2++) ldsm4(Ah[mt2], aB + offA[mt2] + cA);
#pragma unroll
            for (int ng = 0; ng < 4; ng++) {
                uint32_t Bh[4];
                ldsm4(Bh, bB + offB[ng] + cB);
#pragma unroll
                for (int h = 0; h < 2; h++) {
                    int n8 = ng * 2 + h;
                    mma_f16(acc[0][n8], Ah[0], &Bh[h * 2]);
                    mma_f16(acc[1][n8], Ah[1], &Bh[h * 2]);
                }
            }
        }
        __syncthreads();
        if (tid == 0 && ch + 2 < CH_BIG) issue(ch + 2, st);
    }
#pragma unroll
    for (int mt2 = 0; mt2 < 2; mt2++)
#pragma unroll
        for (int half = 0; half < 2; half++) {
            int r = wm + mt2 * 16 + (lane >> 2) + half * 8;
            int pp = mt_local * 64 + r;
            int yq = pp / PADW, xq = pp - yq * PADW;
            bool ok = (yq >= 1) && (yq <= 96) && (xq >= 1) && (xq <= 96);
            if (!ok) continue;
            float* drow = g_conv2 + ((size_t)(b * HWN + (yq - 1) * 96 + xq - 1)) * RS_BIG;
#pragma unroll
            for (int n8 = 0; n8 < 8; n8++) {
                int col = nt * 256 + wn + n8 * 8 + (lane & 3) * 2;
                float2 v = make_float2(acc[mt2][n8][half * 2 + 0] + g_bpack[col],
                                       acc[mt2][n8][half * 2 + 1] + g_bpack[col + 1]);
                *(float2*)&drow[col] = v;
            }
        }
}

__global__ void ln_row(const float* __restrict__ gam, const float* __restrict__ bet) {
    int m = blockIdx.x * 8 + (threadIdx.x >> 5);
    int lane = threadIdx.x & 31;
    const float* src = g_qpre + (size_t)m * 256 + lane * 8;
    float4 a = *(const float4*)src;
    float4 b4 = *(const float4*)(src + 4);
    float v[8] = {a.x, a.y, a.z, a.w, b4.x, b4.y, b4.z, b4.w};
    float s1 = 0.f, s2 = 0.f;
#pragma unroll
    for (int j = 0; j < 8; j++) { s1 += v[j]; s2 += v[j] * v[j]; }
#pragma unroll
    for (int o = 16; o > 0; o >>= 1) {
        s1 += __shfl_xor_sync(0xffffffffu, s1, o);
        s2 += __shfl_xor_sync(0xffffffffu, s2, o);
    }
    float mu = s1 * (1.f / 256.f);
    float rv = rsqrtf(s2 * (1.f / 256.f) - mu * mu + 1e-5f);
#pragma unroll
    for (int j = 0; j < 8; j++) {
        int c = lane * 8 + j;
        v[j] = (v[j] - mu) * rv * __ldg(&gam[c]) + __ldg(&bet[c]);
    }
    __align__(16) __half hv[8];
    cvt8(v, hv);
    *(uint4*)&g_qh16[(size_t)m * 256 + lane * 8] = *(uint4*)hv;
    int b = m / HWN, p = m - b * HWN;
    int y = p / 96, x = p - y * 96;
    size_t r_abs = (size_t)b * PROWS + 128 + (size_t)(y + 1) * PADW + (x + 1);
    int cq = lane >> 3, u = lane & 7;
    uint32_t sw = (uint32_t)(u * 16) ^ (((uint32_t)r_abs & 7) << 4);
    char* hb = (char*)(g_qpad + ((size_t)cq * QROWS + r_abs) * 64);
    *(uint4*)(hb + sw) = *(uint4*)hv;
}

__global__ void support_kernel(const float* __restrict__ sup, const float* __restrict__ inb,
                               const float* __restrict__ gam, const float* __restrict__ bet) {
    __shared__ float xs[2304];
    __shared__ float Wt[32 * 256];
    __shared__ float stats[18];
    int bid = blockIdx.x;
    int b = bid / 3, ex = bid - b * 3;
    int tid = threadIdx.x;
    const float* sp = sup + (size_t)(b * 3 + ex) * 2304;
    for (int i = tid; i < 2304; i += 256) xs[i] = sp[i];
    float acc[9];
    float bia = inb[tid];
#pragma unroll
    for (int pos = 0; pos < 9; pos++) acc[pos] = bia;
    for (int k0 = 0; k0 < 256; k0 += 32) {
        __syncthreads();
        const float4* src = (const float4*)(g_WA + k0 * 256);
        float4* dW = (float4*)Wt;
        for (int i = tid; i < 2048; i += 256) dW[i] = src[i];
        __syncthreads();
#pragma unroll
        for (int kk = 0; kk < 32; kk++) {
            float w = Wt[kk * 256 + tid];
#pragma unroll
            for (int pos = 0; pos < 9; pos++) acc[pos] += w * xs[(k0 + kk) * 9 + pos];
        }
    }
    __syncthreads();
#pragma unroll
    for (int pos = 0; pos < 9; pos++) xs[tid * 9 + pos] = acc[pos];
    __syncthreads();
    if (tid < 9) {
        float s1 = 0.f, s2 = 0.f;
        for (int c = 0; c < 256; c++) { float v = xs[c * 9 + tid]; s1 += v; s2 += v * v; }
        float mu = s1 * (1.f / 256.f);
        stats[tid] = mu;
        stats[9 + tid] = rsqrtf(s2 * (1.f / 256.f) - mu * mu + 1e-5f);
    }
    __syncthreads();
    float mx = -1e30f;
    float g = gam[tid], be = bet[tid];
#pragma unroll
    for (int pos = 0; pos < 9; pos++) {
        float v = (acc[pos] - stats[pos]) * stats[9 + pos] * g + be;
        g_sW[((size_t)(b * 3 + ex) * 256 + tid) * 9 + pos] = v;
        mx = fmaxf(mx, v);
    }
    int r = ex * 2 + (tid >> 7);
    g_pool[(b * 6 + r) * 128 + (tid & 127)] = mx;
}

__global__ void sim0_kernel() {
    __shared__ __align__(16) float psh[6 * 128];
    int b = blockIdx.y;
    int tid = threadIdx.x;
    int lane8 = tid & 7, pl = tid >> 3;
    int pg = blockIdx.x * 32 + pl;
    for (int i = tid; i < 768; i += 256) psh[i] = g_pool[b * 768 + i];
    __syncthreads();
    const __half* qrow = g_qh16 + ((size_t)b * HWN + pg) * 256;
    float acc[6];
#pragma unroll
    for (int r = 0; r < 6; r++) acc[r] = 0.f;
#pragma unroll
    for (int r = 0; r < 6; r++) {
        int g = (r >= 3) ? 1 : 0;
#pragma unroll
        for (int qq = 0; qq < 4; qq++) {
            int f = lane8 + qq * 8;
            uint2 t = *(const uint2*)&qrow[g * 128 + f * 4];
            float2 q0 = __half22float2(*(__half2*)&t.x);
            float2 q1 = __half22float2(*(__half2*)&t.y);
            float4 pv = *(const float4*)&psh[r * 128 + f * 4];
            acc[r] += q0.x * pv.x + q0.y * pv.y + q1.x * pv.z + q1.y * pv.w;
        }
    }
#pragma unroll
    for (int r = 0; r < 6; r++) {
        acc[r] += __shfl_xor_sync(0xffffffffu, acc[r], 1);
        acc[r] += __shfl_xor_sync(0xffffffffu, acc[r], 2);
        acc[r] += __shfl_xor_sync(0xffffffffu, acc[r], 4);
    }
    if (lane8 == 0)
#pragma unroll
        for (int r = 0; r < 6; r++) g_sim[((size_t)b * 24 + r) * HWN + pg] = acc[r];
}

__device__ __forceinline__ void deform_og(
    int og, int py, int px, int dil, int lane8,
    const float* __restrict__ prow, const float* mskrow, const __half* __restrict__ qh,
    const float* wsh, float& a0, float& a1, float& a2, int rbase) {
    int cb = og * 32 + lane8 * 4;
    int cgrp = (og & 3) * 32 + lane8 * 4;
#pragma unroll
    for (int tap = 0; tap < 9; tap++) {
        float dy = prow[og * 18 + tap * 2];
        float dx = prow[og * 18 + tap * 2 + 1];
        float m = mskrow[og * 9 + tap];
        float fy = (float)(py + (tap / 3) * dil - dil) + dy;
        float fx = (float)(px + (tap % 3) * dil - dil) + dx;
        float y0f = floorf(fy), x0f = floorf(fx);
        float wy = fy - y0f, wx = fx - x0f;
        int y0 = (int)y0f, x0 = (int)x0f;
        float w00 = (1.f - wy) * (1.f - wx) * m, w01 = (1.f - wy) * wx * m;
        float w10 = wy * (1.f - wx) * m, w11 = wy * wx * m;
        bool y0v = (unsigned)y0 < 96u, y1v = (unsigned)(y0 + 1) < 96u;
        bool x0v = (unsigned)x0 < 96u, x1v = (unsigned)(x0 + 1) < 96u;
        float vx = 0.f, vy = 0.f, vz = 0.f, vw = 0.f;
#define CORNER(cond, yy, xx, wgt)                                              \
        if (cond) {                                                            \
            uint2 t = *(const uint2*)&qh[(size_t)((yy) * 96 + (xx)) * 256 + cb]; \
            float2 f0 = __half22float2(*(__half2*)&t.x);                       \
            float2 f1 = __half22float2(*(__half2*)&t.y);                       \
            vx += (wgt) * f0.x; vy += (wgt) * f0.y;                            \
            vz += (wgt) * f1.x; vw += (wgt) * f1.y;                            \
        }
        CORNER(y0v && x0v, y0, x0, w00)
        CORNER(y0v && x1v, y0, x0 + 1, w01)
        CORNER(y1v && x0v, y0 + 1, x0, w10)
        CORNER(y1v && x1v, y0 + 1, x0 + 1, w11)
#undef CORNER
        float4 w0 = *(const float4*)&wsh[((rbase + 0) * 9 + tap) * 128 + cgrp];
        a0 += vx * w0.x + vy * w0.y + vz * w0.z + vw * w0.w;
        float4 w1 = *(const float4*)&wsh[((rbase + 1) * 9 + tap) * 128 + cgrp];
        a1 += vx * w1.x + vy * w1.y + vz * w1.z + vw * w1.w;
        float4 w2 = *(const float4*)&wsh[((rbase + 2) * 9 + tap) * 128 + cgrp];
        a2 += vx * w2.x + vy * w2.y + vz * w2.z + vw * w2.w;
    }
}

__global__ void deform_kernel() {
    __shared__ __align__(16) float wsh[6 * 9 * 128];
    __shared__ float msk[32][73];
    int z = blockIdx.z;
    int b = z / 3, dz = z - b * 3;
    int dil = 1 << dz;
    int tid = threadIdx.x;
    int lane8 = tid & 7, pl = tid >> 3;
    int px = blockIdx.x * 8 + (pl & 7);
    int py = blockIdx.y * 4 + (pl >> 3);
    int p = py * 96 + px;
    for (int i = tid; i < 6912; i += 256) {
        int r = i / 1152;
        int rem = i - r * 1152;
        int tap = rem >> 7;
        int cg = rem & 127;
        int ex = r >> 1, half = r & 1;
        wsh[i] = g_sW[((size_t)(b * 3 + ex) * 256 + half * 128 + cg) * 9 + tap];
    }
    const float* prow = g_conv2 + ((size_t)(b * HWN) + p) * RS_BIG + dz * 216;
    // fused softmax over 72 mask channels: thread lane8 handles og=lane8's 9 taps
    {
        const float* mrow = prow + 144;
        float vals[9];
        float mx = -1e30f;
#pragma unroll
        for (int t = 0; t < 9; t++) {
            vals[t] = __ldg(&mrow[lane8 * 9 + t]);
            mx = fmaxf(mx, vals[t]);
        }
        mx = fmaxf(mx, __shfl_xor_sync(0xffffffffu, mx, 1));
        mx = fmaxf(mx, __shfl_xor_sync(0xffffffffu, mx, 2));
        mx = fmaxf(mx, __shfl_xor_sync(0xffffffffu, mx, 4));
        float s = 0.f;
#pragma unroll
        for (int t = 0; t < 9; t++) { vals[t] = __expf(vals[t] - mx); s += vals[t]; }
        s += __shfl_xor_sync(0xffffffffu, s, 1);
        s += __shfl_xor_sync(0xffffffffu, s, 2);
        s += __shfl_xor_sync(0xffffffffu, s, 4);
        float inv = 1.f / s;
#pragma unroll
        for (int t = 0; t < 9; t++) msk[pl][lane8 * 9 + t] = vals[t] * inv;
    }
    __syncthreads();
    const __half* qh = g_qh16 + (size_t)b * HWN * 256;
    const float* mskrow = msk[pl];
    float a0 = 0.f, a1 = 0.f, a2 = 0.f, a3 = 0.f, a4 = 0.f, a5 = 0.f;
#pragma unroll 1
    for (int og = 0; og < 4; og++)
        deform_og(og, py, px, dil, lane8, prow, mskrow, qh, wsh, a0, a1, a2, 0);
#pragma unroll 1
    for (int og = 4; og < 8; og++)
        deform_og(og, py, px, dil, lane8, prow, mskrow, qh, wsh, a3, a4, a5, 3);
    float acc[6] = {a0, a1, a2, a3, a4, a5};
#pragma unroll
    for (int r = 0; r < 6; r++) {
        acc[r] += __shfl_xor_sync(0xffffffffu, acc[r], 1);
        acc[r] += __shfl_xor_sync(0xffffffffu, acc[r], 2);
        acc[r] += __shfl_xor_sync(0xffffffffu, acc[r], 4);
    }
    if (lane8 == 0) {
        size_t obase = ((size_t)b * 24 + 6 + dz * 6) * HWN + p;
#pragma unroll
        for (int r = 0; r < 6; r++) g_sim[obase + (size_t)r * HWN] = acc[r];
    }
}

__global__ void outconv_kernel(const float* __restrict__ ow, const float* __restrict__ ob,
                               float* __restrict__ out) {
    __shared__ float ws[256 * 25];
    __shared__ float st[24 * 65];
    int b = blockIdx.y;
    int m0 = blockIdx.x * 64;
    int tid = threadIdx.x;
    for (int i = tid; i < 6144; i += 256) {
        int oc = i / 24, k = i - oc * 24;
        ws[oc * 25 + k] = ow[i];
    }
    for (int i = tid; i < 24 * 64; i += 256) {
        int ch = i >> 6, j = i & 63;
        st[ch * 65 + j] = g_sim[((size_t)b * 24 + ch) * HWN + m0 + j];
    }
    __syncthreads();
    int j = tid & 63;
    int ocb = (tid >> 6) * 64;
    for (int oc = ocb; oc < ocb + 64; oc++) {
        float a = ob[oc];
#pragma unroll
        for (int k = 0; k < 24; k++) a += ws[oc * 25 + k] * st[k * 65 + j];
        out[((size_t)b * 256 + oc) * HWN + m0 + j] = a;
    }
}

extern "C" void kernel_launch(void* const* d_in, const int* in_sizes, int n_in,
                              void* d_out, int out_size) {
    const float* qf = (const float*)d_in[0];
    const float* sf = (const float*)d_in[1];
    const float* in_w = (const float*)d_in[2];
    const float* in_b = (const float*)d_in[3];
    const float* ln_g = (const float*)d_in[4];
    const float* ln_b = (const float*)d_in[5];
    const float* out_w = (const float*)d_in[6];
    const float* out_b = (const float*)d_in[7];
    const float* offw1 = (const float*)d_in[8];
    const float* offb1 = (const float*)d_in[9];
    const float* mskw1 = (const float*)d_in[10];
    const float* mskb1 = (const float*)d_in[11];
    const float* offw2 = (const float*)d_in[12];
    const float* offb2 = (const float*)d_in[13];
    const float* mskw2 = (const float*)d_in[14];
    const float* mskb2 = (const float*)d_in[15];
    const float* offw4 = (const float*)d_in[16];
    const float* offb4 = (const float*)d_in[17];
    const float* mskw4 = (const float*)d_in[18];
    const float* mskb4 = (const float*)d_in[19];
    float* out = (float*)d_out;

    cudaFuncSetAttribute(gemm_in_k, cudaFuncAttributeMaxDynamicSharedMemorySize, SMEM_IN);
    cudaFuncSetAttribute(gemm_big_k, cudaFuncAttributeMaxDynamicSharedMemorySize, SMEM_BIG);

    pack_wa<<<256, 256>>>(in_w);
    pack_bias<<<3, 256>>>(offb1, mskb1, offb2, mskb2, offb4, mskb4);
    pack_bin<<<CH_IN, 256>>>(in_w);
    pack_bbig<<<dim3(NT_BIG, CH_BIG), 256>>>(offw1, mskw1, offw2, mskw2, offw4, mskw4);
    prep_ain<<<dim3(MT_IN, CH_IN), 256>>>(qf);
    gemm_in_k<<<MT_IN, 256, SMEM_IN>>>(in_b);
    support_kernel<<<6, 256>>>(sf, in_b, ln_g, ln_b);
    ln_row<<<2304, 256>>>(ln_g, ln_b);
    gemm_big_k<<<BB * BT64 * NT_BIG, 256, SMEM_BIG>>>();
    sim0_kernel<<<dim3(288, 2), 256>>>();
    deform_kernel<<<dim3(12, 24, 6), 256>>>();
    outconv_kernel<<<dim3(144, 2), 256>>>(out_w, out_b, out);
}

// round 8
// speedup vs baseline: 5.5333x; 1.0858x over previous
#include <cuda_runtime.h>
#include <cuda_fp16.h>
#include <stdint.h>

#define HWN 9216
#define CN 256
#define BB 2
#define NOUT 648
#define CH_BIG 36
#define CH_IN 4
#define NT_BIG 3
#define MT_IN 144
#define BT64 150
#define PADW 98
#define PROWS 9856
#define QROWS 19712
#define RS_BIG 768

__device__ __align__(128) __half g_qpad[(size_t)4 * QROWS * 64];
__device__ __align__(128) __half g_qh16[(size_t)BB * HWN * 256];
__device__ __align__(128) __half g_Ain[(size_t)MT_IN * CH_IN * 8192];
__device__ __align__(128) __half g_Bbig[(size_t)NT_BIG * CH_BIG * 16384];
__device__ __align__(128) __half g_Bin[(size_t)CH_IN * 16384];
__device__ float g_conv2[(size_t)BB * HWN * RS_BIG];
__device__ float g_WA[CN * CN];
__device__ float g_sW[BB * 3 * CN * 9];
__device__ float g_pool[BB * 6 * 128];
__device__ float g_sim[BB * 24 * HWN];
__device__ __align__(16) float g_bpack[768];

__device__ __forceinline__ uint32_t smem_u32(const void* p) {
    uint32_t a;
    asm("{ .reg .u64 t; cvta.to.shared.u64 t, %1; cvt.u32.u64 %0, t; }" : "=r"(a) : "l"(p));
    return a;
}
#define MBINIT(a, c) asm volatile("mbarrier.init.shared.b64 [%0], %1;" ::"r"(a), "r"(c) : "memory")
#define MBEXPECT(a, b) \
    asm volatile("mbarrier.arrive.expect_tx.shared.b64 _, [%0], %1;" ::"r"(a), "r"(b) : "memory")
__device__ __forceinline__ void mbar_wait(uint32_t mbar, uint32_t parity) {
    asm volatile(
        "{\n\t.reg .pred P;\n\t"
        "LAB_%=:\n\t"
        "mbarrier.try_wait.parity.acquire.cta.shared::cta.b64 P, [%0], %1, 0x989680;\n\t"
        "@!P bra LAB_%=;\n\t}" ::"r"(mbar), "r"(parity) : "memory");
}
__device__ __forceinline__ void bulk_g2s(uint32_t dst, const void* src, uint32_t bytes, uint32_t mbar) {
    asm volatile(
        "cp.async.bulk.shared::cluster.global.mbarrier::complete_tx::bytes [%0], [%1], %2, [%3];"
        ::"r"(dst), "l"(src), "r"(bytes), "r"(mbar) : "memory");
}
__device__ __forceinline__ void ldsm4(uint32_t* r, uint32_t addr) {
    asm volatile("ldmatrix.sync.aligned.m8n8.x4.shared.b16 {%0,%1,%2,%3}, [%4];"
                 : "=r"(r[0]), "=r"(r[1]), "=r"(r[2]), "=r"(r[3]) : "r"(addr));
}
__device__ __forceinline__ void mma_f16(float* c, const uint32_t* a, const uint32_t* b) {
    asm volatile(
        "mma.sync.aligned.m16n8k16.row.col.f32.f16.f16.f32 "
        "{%0,%1,%2,%3}, {%4,%5,%6,%7}, {%8,%9}, {%0,%1,%2,%3};"
        : "+f"(c[0]), "+f"(c[1]), "+f"(c[2]), "+f"(c[3])
        : "r"(a[0]), "r"(a[1]), "r"(a[2]), "r"(a[3]), "r"(b[0]), "r"(b[1]));
}
__device__ __forceinline__ void cvt8(const float* v, __half* hv) {
#pragma unroll
    for (int j = 0; j < 8; j++) hv[j] = __float2half_rn(v[j]);
}

__global__ void pack_wa(const float* __restrict__ inw) {
    int idx = blockIdx.x * 256 + threadIdx.x;
    int k = idx >> 8, n = idx & 255;
    g_WA[k * CN + n] = inw[n * CN + k];
}

// ---- merged prep: bias(1) | bin(4) | bbig(108) | ain(576) | support(6) ----
__global__ void prep_all(const float* __restrict__ qf, const float* __restrict__ sup,
                         const float* __restrict__ inw, const float* __restrict__ inb,
                         const float* __restrict__ gam, const float* __restrict__ bet,
                         const float* __restrict__ ow1, const float* __restrict__ mw1,
                         const float* __restrict__ ow2, const float* __restrict__ mw2,
                         const float* __restrict__ ow4, const float* __restrict__ mw4,
                         const float* __restrict__ ob1, const float* __restrict__ mb1,
                         const float* __restrict__ ob2, const float* __restrict__ mb2,
                         const float* __restrict__ ob4, const float* __restrict__ mb4) {
    __shared__ float xs[2304];
    __shared__ float Wt[32 * 256];
    __shared__ float stats[18];
    int bx = blockIdx.x;
    int tid = threadIdx.x;
    if (bx == 0) {
        for (int idx = tid; idx < 768; idx += 256) {
            float v = 0.f;
            if (idx < NOUT) {
                int d = idx / 216, r = idx - d * 216;
                const float* bb = (r < 144) ? (d == 0 ? ob1 : d == 1 ? ob2 : ob4)
                                            : (d == 0 ? mb1 : d == 1 ? mb2 : mb4);
                v = bb[(r < 144) ? r : r - 144];
            }
            g_bpack[idx] = v;
        }
        return;
    }
    if (bx < 5) {
        int chunk = bx - 1;
        int c0 = chunk * 64;
        char* dst = (char*)(g_Bin + (size_t)chunk * 16384);
#pragma unroll
        for (int i = 0; i < 8; i++) {
            int unit = i * 256 + tid;
            int r = unit >> 3, u = unit & 7;
            float v[8];
#pragma unroll
            for (int j = 0; j < 8; j++) v[j] = inw[(size_t)r * 256 + c0 + u * 8 + j];
            __align__(16) __half hv[8];
            cvt8(v, hv);
            uint32_t off = r * 128 + u * 16;
            uint32_t sw = off ^ ((off >> 3) & 0x70);
            *(uint4*)(dst + sw) = *(uint4*)hv;
        }
        return;
    }
    if (bx < 113) {
        int t = bx - 5;
        int nt = t % 3, chunk = t / 3;
        int tap = chunk >> 2;
        int c0 = (chunk & 3) * 64;
        char* dst = (char*)(g_Bbig + (size_t)(nt * CH_BIG + chunk) * 16384);
#pragma unroll
        for (int i = 0; i < 8; i++) {
            int unit = i * 256 + tid;
            int r = unit >> 3, u = unit & 7;
            int n = nt * 256 + r;
            float v[8];
#pragma unroll
            for (int j = 0; j < 8; j++) v[j] = 0.f;
            if (n < NOUT) {
                int d = n / 216, rr = n - d * 216;
                const float* w = (rr < 144) ? (d == 0 ? ow1 : d == 1 ? ow2 : ow4)
                                            : (d == 0 ? mw1 : d == 1 ? mw2 : mw4);
                int oc = (rr < 144) ? rr : rr - 144;
#pragma unroll
                for (int j = 0; j < 8; j++)
                    v[j] = w[(size_t)oc * 2304 + (size_t)(c0 + u * 8 + j) * 9 + tap];
            }
            __align__(16) __half hv[8];
            cvt8(v, hv);
            uint32_t off = r * 128 + u * 16;
            uint32_t sw = off ^ ((off >> 3) & 0x70);
            *(uint4*)(dst + sw) = *(uint4*)hv;
        }
        return;
    }
    if (bx < 689) {
        int t = bx - 113;
        int mt = t % MT_IN, chunk = t / MT_IN;
        int c0 = chunk * 64;
        char* dst = (char*)(g_Ain + (size_t)(mt * CH_IN + chunk) * 8192);
#pragma unroll
        for (int i = 0; i < 4; i++) {
            int unit = i * 256 + tid;
            int r = unit & 127, u = unit >> 7;
            int m = mt * 128 + r;
            int b = m / HWN, p = m - b * HWN;
            float v[8];
#pragma unroll
            for (int j = 0; j < 8; j++) v[j] = qf[((size_t)b * CN + c0 + u * 8 + j) * HWN + p];
            __align__(16) __half hv[8];
            cvt8(v, hv);
            uint32_t off = r * 128 + u * 16;
            uint32_t sw = off ^ ((off >> 3) & 0x70);
            *(uint4*)(dst + sw) = *(uint4*)hv;
        }
        return;
    }
    // support branch
    {
        int bid = bx - 689;
        int b = bid / 3, ex = bid - b * 3;
        const float* sp = sup + (size_t)(b * 3 + ex) * 2304;
        for (int i = tid; i < 2304; i += 256) xs[i] = sp[i];
        float acc[9];
        float bia = inb[tid];
#pragma unroll
        for (int pos = 0; pos < 9; pos++) acc[pos] = bia;
        for (int k0 = 0; k0 < 256; k0 += 32) {
            __syncthreads();
            const float4* src = (const float4*)(g_WA + k0 * 256);
            float4* dW = (float4*)Wt;
            for (int i = tid; i < 2048; i += 256) dW[i] = src[i];
            __syncthreads();
#pragma unroll
            for (int kk = 0; kk < 32; kk++) {
                float w = Wt[kk * 256 + tid];
#pragma unroll
                for (int pos = 0; pos < 9; pos++) acc[pos] += w * xs[(k0 + kk) * 9 + pos];
            }
        }
        __syncthreads();
#pragma unroll
        for (int pos = 0; pos < 9; pos++) xs[tid * 9 + pos] = acc[pos];
        __syncthreads();
        if (tid < 9) {
            float s1 = 0.f, s2 = 0.f;
            for (int c = 0; c < 256; c++) { float v = xs[c * 9 + tid]; s1 += v; s2 += v * v; }
            float mu = s1 * (1.f / 256.f);
            stats[tid] = mu;
            stats[9 + tid] = rsqrtf(s2 * (1.f / 256.f) - mu * mu + 1e-5f);
        }
        __syncthreads();
        float mx = -1e30f;
        float g = gam[tid], be = bet[tid];
#pragma unroll
        for (int pos = 0; pos < 9; pos++) {
            float v = (acc[pos] - stats[pos]) * stats[9 + pos] * g + be;
            g_sW[((size_t)(b * 3 + ex) * 256 + tid) * 9 + pos] = v;
            mx = fmaxf(mx, v);
        }
        int r = ex * 2 + (tid >> 7);
        g_pool[(b * 6 + r) * 128 + (tid & 127)] = mx;
    }
}

// ---- in-projection GEMM + fused LayerNorm epilogue ----
#define STGI 49152
#define SMEM_IN (1024 + 3 * STGI)
__global__ __launch_bounds__(256, 1) void gemm_in_k(const float* __restrict__ bias,
                                                    const float* __restrict__ gam,
                                                    const float* __restrict__ bet) {
    extern __shared__ char smraw[];
    char* basep = (char*)(((uintptr_t)smraw + 1023) & ~(uintptr_t)1023);
    uint32_t sb = smem_u32(basep);
    int mt = blockIdx.x;
    int tid = threadIdx.x, wid = tid >> 5, lane = tid & 31;
    int wm = (wid & 3) * 32, wn = (wid >> 2) * 128;
    uint32_t FULLB = sb, STG = sb + 1024;
    if (tid == 0)
        for (int s = 0; s < 3; s++) MBINIT(FULLB + s * 8, 1);
    __syncthreads();
    auto issue = [&](int ch, int st) {
        uint32_t S = STG + st * STGI;
        MBEXPECT(FULLB + st * 8, 49152u);
        bulk_g2s(S, g_Ain + (size_t)(mt * CH_IN + ch) * 8192, 16384u, FULLB + st * 8);
        bulk_g2s(S + 16384, g_Bin + (size_t)ch * 16384, 32768u, FULLB + st * 8);
    };
    if (tid == 0) { issue(0, 0); issue(1, 1); issue(2, 2); }
    float acc[2][16][4];
#pragma unroll
    for (int a = 0; a < 2; a++)
#pragma unroll
        for (int n = 0; n < 16; n++)
#pragma unroll
            for (int c = 0; c < 4; c++) acc[a][n][c] = 0.f;
    int x7 = lane & 7, kuA = lane >> 4, kuB = (lane >> 3) & 1;
    uint32_t offA[2], offB[8];
#pragma unroll
    for (int mt2 = 0; mt2 < 2; mt2++)
        offA[mt2] = (uint32_t)(wm + mt2 * 16 + ((lane >> 3) & 1) * 8 + x7) * 128u;
#pragma unroll
    for (int ng = 0; ng < 8; ng++)
        offB[ng] = (uint32_t)(wn + ng * 16 + ((lane >> 4) << 3) + x7) * 128u;
    for (int ch = 0; ch < CH_IN; ch++) {
        int st = ch % 3;
        mbar_wait(FULLB + st * 8, (uint32_t)((ch / 3) & 1));
        uint32_t aB = STG + st * STGI, bB = aB + 16384;
#pragma unroll
        for (int ks = 0; ks < 4; ks++) {
            uint32_t cA = (uint32_t)(((ks * 2 + kuA) ^ x7) << 4);
            uint32_t cB = (uint32_t)(((ks * 2 + kuB) ^ x7) << 4);
            uint32_t Ah[2][4];
#pragma unroll
            for (int mt2 = 0; mt2 < 2; mt2++) ldsm4(Ah[mt2], aB + offA[mt2] + cA);
#pragma unroll
            for (int ng = 0; ng < 8; ng++) {
                uint32_t Bh[4];
                ldsm4(Bh, bB + offB[ng] + cB);
#pragma unroll
                for (int h = 0; h < 2; h++) {
                    int n8 = ng * 2 + h;
                    mma_f16(acc[0][n8], Ah[0], &Bh[h * 2]);
                    mma_f16(acc[1][n8], Ah[1], &Bh[h * 2]);
                }
            }
        }
        __syncthreads();
        if (tid == 0 && ch + 3 < CH_IN) issue(ch + 3, st);
    }
    // stage fp32 tile (128 x 264 stride) in pipeline smem
    float* tile = (float*)(basep + 1024);
#pragma unroll
    for (int mt2 = 0; mt2 < 2; mt2++)
#pragma unroll
        for (int half = 0; half < 2; half++) {
            int r = wm + mt2 * 16 + (lane >> 2) + half * 8;
            float* trow = tile + (size_t)r * 264;
#pragma unroll
            for (int n8 = 0; n8 < 16; n8++) {
                int col = wn + n8 * 8 + (lane & 3) * 2;
                float2 v = make_float2(acc[mt2][n8][half * 2 + 0] + bias[col],
                                       acc[mt2][n8][half * 2 + 1] + bias[col + 1]);
                *(float2*)&trow[col] = v;
            }
        }
    __syncthreads();
    // fused LayerNorm: warp handles 16 rows
    float gv[8], bv[8];
#pragma unroll
    for (int j = 0; j < 8; j++) {
        int c = lane * 8 + j;
        gv[j] = __ldg(&gam[c]);
        bv[j] = __ldg(&bet[c]);
    }
    for (int rr = 0; rr < 16; rr++) {
        int row = wid * 16 + rr;
        const float* trow = tile + (size_t)row * 264 + lane * 8;
        float4 a = *(const float4*)trow;
        float4 b4 = *(const float4*)(trow + 4);
        float v[8] = {a.x, a.y, a.z, a.w, b4.x, b4.y, b4.z, b4.w};
        float s1 = 0.f, s2 = 0.f;
#pragma unroll
        for (int j = 0; j < 8; j++) { s1 += v[j]; s2 += v[j] * v[j]; }
#pragma unroll
        for (int o = 16; o > 0; o >>= 1) {
            s1 += __shfl_xor_sync(0xffffffffu, s1, o);
            s2 += __shfl_xor_sync(0xffffffffu, s2, o);
        }
        float mu = s1 * (1.f / 256.f);
        float rv = rsqrtf(s2 * (1.f / 256.f) - mu * mu + 1e-5f);
#pragma unroll
        for (int j = 0; j < 8; j++) v[j] = (v[j] - mu) * rv * gv[j] + bv[j];
        __align__(16) __half hv[8];
        cvt8(v, hv);
        int m = mt * 128 + row;
        *(uint4*)&g_qh16[(size_t)m * 256 + lane * 8] = *(uint4*)hv;
        int b = m / HWN, p = m - b * HWN;
        int y = p / 96, x = p - y * 96;
        size_t r_abs = (size_t)b * PROWS + 128 + (size_t)(y + 1) * PADW + (x + 1);
        int cq = lane >> 3, u = lane & 7;
        uint32_t sw = (uint32_t)(u * 16) ^ (((uint32_t)r_abs & 7) << 4);
        char* hb = (char*)(g_qpad + ((size_t)cq * QROWS + r_abs) * 64);
        *(uint4*)(hb + sw) = *(uint4*)hv;
    }
}

// ---- big conv GEMM: M64 N256 K2304, 2-stage, 2 CTAs/SM ----
#define STGB 40960
#define SMEM_BIG (1024 + 2 * STGB)
__global__ __launch_bounds__(256, 2) void gemm_big_k() {
    extern __shared__ char smraw[];
    char* basep = (char*)(((uintptr_t)smraw + 1023) & ~(uintptr_t)1023);
    uint32_t sb = smem_u32(basep);
    int bx = blockIdx.x;
    int mt = bx / NT_BIG, nt = bx - (bx / NT_BIG) * NT_BIG;
    int b = mt / BT64, mt_local = mt - b * BT64;
    size_t arowbase = (size_t)b * PROWS + 128 + (size_t)mt_local * 64;
    int tid = threadIdx.x, wid = tid >> 5, lane = tid & 31;
    int wm = (wid & 1) * 32, wn = (wid >> 1) * 64;
    uint32_t FULLB = sb, STG = sb + 1024;
    if (tid == 0)
        for (int s = 0; s < 2; s++) MBINIT(FULLB + s * 8, 1);
    __syncthreads();
    auto issue = [&](int ch, int st) {
        uint32_t S = STG + st * STGB;
        MBEXPECT(FULLB + st * 8, 40960u);
        int tap = ch >> 2, cq = ch & 3;
        int shift = (tap / 3 - 1) * PADW + (tap % 3 - 1);
        size_t row0 = arowbase + shift;
        bulk_g2s(S, g_qpad + ((size_t)cq * QROWS + row0) * 64, 8192u, FULLB + st * 8);
        bulk_g2s(S + 8192, g_Bbig + (size_t)(nt * CH_BIG + ch) * 16384, 32768u, FULLB + st * 8);
    };
    if (tid == 0) { issue(0, 0); issue(1, 1); }
    float acc[2][8][4];
#pragma unroll
    for (int a = 0; a < 2; a++)
#pragma unroll
        for (int n = 0; n < 8; n++)
#pragma unroll
            for (int c = 0; c < 4; c++) acc[a][n][c] = 0.f;
    int x7 = lane & 7, kuA = lane >> 4, kuB = (lane >> 3) & 1;
    uint32_t offA[2], offB[4];
#pragma unroll
    for (int mt2 = 0; mt2 < 2; mt2++)
        offA[mt2] = (uint32_t)(wm + mt2 * 16 + ((lane >> 3) & 1) * 8 + x7) * 128u;
#pragma unroll
    for (int ng = 0; ng < 4; ng++)
        offB[ng] = (uint32_t)(wn + ng * 16 + ((lane >> 4) << 3) + x7) * 128u;
    for (int ch = 0; ch < CH_BIG; ch++) {
        int st = ch & 1;
        mbar_wait(FULLB + st * 8, (uint32_t)((ch >> 1) & 1));
        uint32_t aB = STG + st * STGB, bB = aB + 8192;
        int tap = ch >> 2;
        int shift = (tap / 3 - 1) * PADW + (tap % 3 - 1);
        int xA = (x7 + shift) & 7;
#pragma unroll
        for (int ks = 0; ks < 4; ks++) {
            uint32_t cA = (uint32_t)(((ks * 2 + kuA) ^ xA) << 4);
            uint32_t cB = (uint32_t)(((ks * 2 + kuB) ^ x7) << 4);
            uint32_t Ah[2][4];
#pragma unroll
            for (int mt2 = 0; mt2 < 2; mt2++) ldsm4(Ah[mt2], aB + offA[mt2] + cA);
#pragma unroll
            for (int ng = 0; ng < 4; ng++) {
                uint32_t Bh[4];
                ldsm4(Bh, bB + offB[ng] + cB);
#pragma unroll
                for (int h = 0; h < 2; h++) {
                    int n8 = ng * 2 + h;
                    mma_f16(acc[0][n8], Ah[0], &Bh[h * 2]);
                    mma_f16(acc[1][n8], Ah[1], &Bh[h * 2]);
                }
            }
        }
        __syncthreads();
        if (tid == 0 && ch + 2 < CH_BIG) issue(ch + 2, st);
    }
#pragma unroll
    for (int mt2 = 0; mt2 < 2; mt2++)
#pragma unroll
        for (int half = 0; half < 2; half++) {
            int r = wm + mt2 * 16 + (lane >> 2) + half * 8;
            int pp = mt_local * 64 + r;
            int yq = pp / PADW, xq = pp - yq * PADW;
            bool ok = (yq >= 1) && (yq <= 96) && (xq >= 1) && (xq <= 96);
            if (!ok) continue;
            float* drow = g_conv2 + ((size_t)(b * HWN + (yq - 1) * 96 + xq - 1)) * RS_BIG;
#pragma unroll
            for (int n8 = 0; n8 < 8; n8++) {
                int col = nt * 256 + wn + n8 * 8 + (lane & 3) * 2;
                float2 v = make_float2(acc[mt2][n8][half * 2 + 0] + g_bpack[col],
                                       acc[mt2][n8][half * 2 + 1] + g_bpack[col + 1]);
                *(float2*)&drow[col] = v;
            }
        }
}

__device__ __forceinline__ void deform_og(
    int og, int py, int px, int dil, int lane8,
    const float* __restrict__ prow, const float* mskrow, const __half* __restrict__ qh,
    const float* wsh, float& a0, float& a1, float& a2, int rbase) {
    int cb = og * 32 + lane8 * 4;
    int cgrp = (og & 3) * 32 + lane8 * 4;
#pragma unroll
    for (int tap = 0; tap < 9; tap++) {
        float dy = prow[og * 18 + tap * 2];
        float dx = prow[og * 18 + tap * 2 + 1];
        float m = mskrow[og * 9 + tap];
        float fy = (float)(py + (tap / 3) * dil - dil) + dy;
        float fx = (float)(px + (tap % 3) * dil - dil) + dx;
        float y0f = floorf(fy), x0f = floorf(fx);
        float wy = fy - y0f, wx = fx - x0f;
        int y0 = (int)y0f, x0 = (int)x0f;
        float w00 = (1.f - wy) * (1.f - wx) * m, w01 = (1.f - wy) * wx * m;
        float w10 = wy * (1.f - wx) * m, w11 = wy * wx * m;
        bool y0v = (unsigned)y0 < 96u, y1v = (unsigned)(y0 + 1) < 96u;
        bool x0v = (unsigned)x0 < 96u, x1v = (unsigned)(x0 + 1) < 96u;
        float vx = 0.f, vy = 0.f, vz = 0.f, vw = 0.f;
#define CORNER(cond, yy, xx, wgt)                                                \
        if (cond) {                                                              \
            uint2 t = *(const uint2*)&qh[(size_t)((yy) * 96 + (xx)) * 256 + cb]; \
            float2 f0 = __half22float2(*(__half2*)&t.x);                         \
            float2 f1 = __half22float2(*(__half2*)&t.y);                         \
            vx += (wgt) * f0.x; vy += (wgt) * f0.y;                              \
            vz += (wgt) * f1.x; vw += (wgt) * f1.y;                              \
        }
        CORNER(y0v && x0v, y0, x0, w00)
        CORNER(y0v && x1v, y0, x0 + 1, w01)
        CORNER(y1v && x0v, y0 + 1, x0, w10)
        CORNER(y1v && x1v, y0 + 1, x0 + 1, w11)
#undef CORNER
        float4 w0 = *(const float4*)&wsh[((rbase + 0) * 9 + tap) * 128 + cgrp];
        a0 += vx * w0.x + vy * w0.y + vz * w0.z + vw * w0.w;
        float4 w1 = *(const float4*)&wsh[((rbase + 1) * 9 + tap) * 128 + cgrp];
        a1 += vx * w1.x + vy * w1.y + vz * w1.z + vw * w1.w;
        float4 w2 = *(const float4*)&wsh[((rbase + 2) * 9 + tap) * 128 + cgrp];
        a2 += vx * w2.x + vy * w2.y + vz * w2.z + vw * w2.w;
    }
}

// ---- merged deform (1728 blocks) + sim0 (576 blocks) ----
__global__ void deform_sim0() {
    __shared__ __align__(16) char shbuf[6 * 9 * 128 * 4 + 32 * 73 * 4];
    int bx = blockIdx.x;
    int tid = threadIdx.x;
    int lane8 = tid & 7, pl = tid >> 3;
    if (bx < 1728) {
        float* wsh = (float*)shbuf;
        float (*msk)[73] = (float(*)[73])(shbuf + 6 * 9 * 128 * 4);
        int i0 = bx % 12;
        int rest = bx / 12;
        int j0 = rest % 24;
        int z = rest / 24;
        int b = z / 3, dz = z - b * 3;
        int dil = 1 << dz;
        int px = i0 * 8 + (pl & 7);
        int py = j0 * 4 + (pl >> 3);
        int p = py * 96 + px;
        for (int i = tid; i < 6912; i += 256) {
            int r = i / 1152;
            int rem = i - r * 1152;
            int tap = rem >> 7;
            int cg = rem & 127;
            int ex = r >> 1, half = r & 1;
            wsh[i] = g_sW[((size_t)(b * 3 + ex) * 256 + half * 128 + cg) * 9 + tap];
        }
        const float* prow = g_conv2 + ((size_t)(b * HWN) + p) * RS_BIG + dz * 216;
        {
            const float* mrow = prow + 144;
            float vals[9];
            float mx = -1e30f;
#pragma unroll
            for (int t = 0; t < 9; t++) {
                vals[t] = __ldg(&mrow[lane8 * 9 + t]);
                mx = fmaxf(mx, vals[t]);
            }
            mx = fmaxf(mx, __shfl_xor_sync(0xffffffffu, mx, 1));
            mx = fmaxf(mx, __shfl_xor_sync(0xffffffffu, mx, 2));
            mx = fmaxf(mx, __shfl_xor_sync(0xffffffffu, mx, 4));
            float s = 0.f;
#pragma unroll
            for (int t = 0; t < 9; t++) { vals[t] = __expf(vals[t] - mx); s += vals[t]; }
            s += __shfl_xor_sync(0xffffffffu, s, 1);
            s += __shfl_xor_sync(0xffffffffu, s, 2);
            s += __shfl_xor_sync(0xffffffffu, s, 4);
            float inv = 1.f / s;
#pragma unroll
            for (int t = 0; t < 9; t++) msk[pl][lane8 * 9 + t] = vals[t] * inv;
        }
        __syncthreads();
        const __half* qh = g_qh16 + (size_t)b * HWN * 256;
        const float* mskrow = msk[pl];
        float a0 = 0.f, a1 = 0.f, a2 = 0.f, a3 = 0.f, a4 = 0.f, a5 = 0.f;
#pragma unroll 1
        for (int og = 0; og < 4; og++)
            deform_og(og, py, px, dil, lane8, prow, mskrow, qh, wsh, a0, a1, a2, 0);
#pragma unroll 1
        for (int og = 4; og < 8; og++)
            deform_og(og, py, px, dil, lane8, prow, mskrow, qh, wsh, a3, a4, a5, 3);
        float acc[6] = {a0, a1, a2, a3, a4, a5};
#pragma unroll
        for (int r = 0; r < 6; r++) {
            acc[r] += __shfl_xor_sync(0xffffffffu, acc[r], 1);
            acc[r] += __shfl_xor_sync(0xffffffffu, acc[r], 2);
            acc[r] += __shfl_xor_sync(0xffffffffu, acc[r], 4);
        }
        if (lane8 == 0) {
            size_t obase = ((size_t)b * 24 + 6 + dz * 6) * HWN + p;
#pragma unroll
            for (int r = 0; r < 6; r++) g_sim[obase + (size_t)r * HWN] = acc[r];
        }
    } else {
        float* psh = (float*)shbuf;
        int s = bx - 1728;
        int b = s / 288;
        int pg = (s - b * 288) * 32 + pl;
        for (int i = tid; i < 768; i += 256) psh[i] = g_pool[b * 768 + i];
        __syncthreads();
        const __half* qrow = g_qh16 + ((size_t)b * HWN + pg) * 256;
        float acc[6];
#pragma unroll
        for (int r = 0; r < 6; r++) acc[r] = 0.f;
#pragma unroll
        for (int r = 0; r < 6; r++) {
            int g = (r >= 3) ? 1 : 0;
#pragma unroll
            for (int qq = 0; qq < 4; qq++) {
                int f = lane8 + qq * 8;
                uint2 t = *(const uint2*)&qrow[g * 128 + f * 4];
                float2 q0 = __half22float2(*(__half2*)&t.x);
                float2 q1 = __half22float2(*(__half2*)&t.y);
                float4 pv = *(const float4*)&psh[r * 128 + f * 4];
                acc[r] += q0.x * pv.x + q0.y * pv.y + q1.x * pv.z + q1.y * pv.w;
            }
        }
#pragma unroll
        for (int r = 0; r < 6; r++) {
            acc[r] += __shfl_xor_sync(0xffffffffu, acc[r], 1);
            acc[r] += __shfl_xor_sync(0xffffffffu, acc[r], 2);
            acc[r] += __shfl_xor_sync(0xffffffffu, acc[r], 4);
        }
        if (lane8 == 0)
#pragma unroll
            for (int r = 0; r < 6; r++) g_sim[((size_t)b * 24 + r) * HWN + pg] = acc[r];
    }
}

__global__ void outconv_kernel(const float* __restrict__ ow, const float* __restrict__ ob,
                               float* __restrict__ out) {
    __shared__ float ws[256 * 25];
    __shared__ float st[24 * 65];
    int b = blockIdx.y;
    int m0 = blockIdx.x * 64;
    int tid = threadIdx.x;
    for (int i = tid; i < 6144; i += 256) {
        int oc = i / 24, k = i - oc * 24;
        ws[oc * 25 + k] = ow[i];
    }
    for (int i = tid; i < 24 * 64; i += 256) {
        int ch = i >> 6, j = i & 63;
        st[ch * 65 + j] = g_sim[((size_t)b * 24 + ch) * HWN + m0 + j];
    }
    __syncthreads();
    int j = tid & 63;
    int ocb = (tid >> 6) * 64;
    for (int oc = ocb; oc < ocb + 64; oc++) {
        float a = ob[oc];
#pragma unroll
        for (int k = 0; k < 24; k++) a += ws[oc * 25 + k] * st[k * 65 + j];
        out[((size_t)b * 256 + oc) * HWN + m0 + j] = a;
    }
}

extern "C" void kernel_launch(void* const* d_in, const int* in_sizes, int n_in,
                              void* d_out, int out_size) {
    const float* qf = (const float*)d_in[0];
    const float* sf = (const float*)d_in[1];
    const float* in_w = (const float*)d_in[2];
    const float* in_b = (const float*)d_in[3];
    const float* ln_g = (const float*)d_in[4];
    const float* ln_b = (const float*)d_in[5];
    const float* out_w = (const float*)d_in[6];
    const float* out_b = (const float*)d_in[7];
    const float* offw1 = (const float*)d_in[8];
    const float* offb1 = (const float*)d_in[9];
    const float* mskw1 = (const float*)d_in[10];
    const float* mskb1 = (const float*)d_in[11];
    const float* offw2 = (const float*)d_in[12];
    const float* offb2 = (const float*)d_in[13];
    const float* mskw2 = (const float*)d_in[14];
    const float* mskb2 = (const float*)d_in[15];
    const float* offw4 = (const float*)d_in[16];
    const float* offb4 = (const float*)d_in[17];
    const float* mskw4 = (const float*)d_in[18];
    const float* mskb4 = (const float*)d_in[19];
    float* out = (float*)d_out;

    cudaFuncSetAttribute(gemm_in_k, cudaFuncAttributeMaxDynamicSharedMemorySize, SMEM_IN);
    cudaFuncSetAttribute(gemm_big_k, cudaFuncAttributeMaxDynamicSharedMemorySize, SMEM_BIG);

    pack_wa<<<256, 256>>>(in_w);
    prep_all<<<695, 256>>>(qf, sf, in_w, in_b, ln_g, ln_b,
                           offw1, mskw1, offw2, mskw2, offw4, mskw4,
                           offb1, mskb1, offb2, mskb2, offb4, mskb4);
    gemm_in_k<<<MT_IN, 256, SMEM_IN>>>(in_b, ln_g, ln_b);
    gemm_big_k<<<BB * BT64 * NT_BIG, 256, SMEM_BIG>>>();
    deform_sim0<<<2304, 256>>>();
    outconv_kernel<<<dim3(144, 2), 256>>>(out_w, out_b, out);
}